// round 1
// baseline (speedup 1.0000x reference)
#include <cuda_runtime.h>
#include <math.h>

// ---------------------------------------------------------------------------
// Problem constants: B=4, T=1024, C=1024, H=16, D=64, F=4096, M=B*T=4096
// ---------------------------------------------------------------------------
#define M_ROWS 4096
#define C_DIM  1024
#define T_SEQ  1024
#define H_HEADS 16
#define D_HEAD 64
#define F_DIM  4096

// Scratch (device globals — allocation-free per harness rules)
__device__ float g_h   [M_ROWS * C_DIM];      // LN outputs (reused 3x)
__device__ float g_qkv [M_ROWS * 3 * C_DIM];
__device__ float g_attn[M_ROWS * C_DIM];      // attention out (reused 2x)
__device__ float g_x1  [M_ROWS * C_DIM];
__device__ float g_x2  [M_ROWS * C_DIM];
__device__ float g_q2  [M_ROWS * C_DIM];
__device__ float g_kv  [M_ROWS * 2 * C_DIM];
__device__ float g_ffn [M_ROWS * F_DIM];

// ---------------------------------------------------------------------------
// LayerNorm over C=1024, one block per row, 256 threads x float4
// ---------------------------------------------------------------------------
__global__ void __launch_bounds__(256) ln_kernel(
    const float* __restrict__ x, const float* __restrict__ g,
    const float* __restrict__ b, float* __restrict__ out)
{
    int row = blockIdx.x;
    int tid = threadIdx.x;
    float4 v = ((const float4*)(x + (size_t)row * C_DIM))[tid];
    float s  = v.x + v.y + v.z + v.w;
    float s2 = v.x*v.x + v.y*v.y + v.z*v.z + v.w*v.w;
    __shared__ float red[64];
    #pragma unroll
    for (int o = 16; o; o >>= 1) {
        s  += __shfl_xor_sync(0xffffffffu, s,  o);
        s2 += __shfl_xor_sync(0xffffffffu, s2, o);
    }
    int warp = tid >> 5;
    if ((tid & 31) == 0) { red[warp] = s; red[32 + warp] = s2; }
    __syncthreads();
    if (tid < 32) {
        s  = (tid < 8) ? red[tid]      : 0.f;
        s2 = (tid < 8) ? red[32 + tid] : 0.f;
        #pragma unroll
        for (int o = 4; o; o >>= 1) {
            s  += __shfl_xor_sync(0xffffffffu, s,  o);
            s2 += __shfl_xor_sync(0xffffffffu, s2, o);
        }
        if (tid == 0) { red[0] = s; red[32] = s2; }
    }
    __syncthreads();
    float mean = red[0]  * (1.0f / C_DIM);
    float var  = red[32] * (1.0f / C_DIM) - mean * mean;
    float inv  = rsqrtf(var + 1e-5f);
    float4 gv = ((const float4*)g)[tid];
    float4 bv = ((const float4*)b)[tid];
    float4 ov;
    ov.x = (v.x - mean) * inv * gv.x + bv.x;
    ov.y = (v.y - mean) * inv * gv.y + bv.y;
    ov.z = (v.z - mean) * inv * gv.z + bv.z;
    ov.w = (v.w - mean) * inv * gv.w + bv.w;
    ((float4*)(out + (size_t)row * C_DIM))[tid] = ov;
}

// ---------------------------------------------------------------------------
// Tiled SGEMM: C[M,N] = A[M,K] @ B[K,N] + bias [+ res | gelu]
// BM=BN=128, BK=8, 256 threads, 8x8 per-thread tile.
// All M,N,K in this problem are multiples of the tile dims -> no bounds checks.
// EPI: 0 = bias, 1 = bias + residual, 2 = bias + exact GELU
// ---------------------------------------------------------------------------
template<int EPI>
__global__ void __launch_bounds__(256) sgemm_kernel(
    const float* __restrict__ A, const float* __restrict__ B,
    const float* __restrict__ bias, const float* __restrict__ res,
    float* __restrict__ C, int M, int N, int K)
{
    __shared__ float As[8][128];
    __shared__ float Bs[8][128];
    int tid  = threadIdx.x;
    int brow = blockIdx.y, bcol = blockIdx.x;
    const float* Ab = A + (size_t)brow * 128 * K;
    const float* Bb = B + (size_t)bcol * 128;

    int arow = tid >> 1;             // 0..127
    int acol = (tid & 1) * 4;        // 0 or 4
    int brw  = tid >> 5;             // 0..7
    int bcl  = (tid & 31) * 4;       // 0..124
    int ty   = tid >> 4, tx = tid & 15;

    float acc[8][8];
    #pragma unroll
    for (int i = 0; i < 8; i++)
        #pragma unroll
        for (int j = 0; j < 8; j++) acc[i][j] = 0.f;

    for (int k0 = 0; k0 < K; k0 += 8) {
        float4 av = *(const float4*)(Ab + (size_t)arow * K + k0 + acol);
        As[acol + 0][arow] = av.x;
        As[acol + 1][arow] = av.y;
        As[acol + 2][arow] = av.z;
        As[acol + 3][arow] = av.w;
        *(float4*)(&Bs[brw][bcl]) = *(const float4*)(Bb + (size_t)(k0 + brw) * N + bcl);
        __syncthreads();
        #pragma unroll
        for (int k = 0; k < 8; k++) {
            float ar[8], br[8];
            #pragma unroll
            for (int i = 0; i < 8; i++) ar[i] = As[k][ty * 8 + i];
            #pragma unroll
            for (int j = 0; j < 8; j++) br[j] = Bs[k][tx * 8 + j];
            #pragma unroll
            for (int i = 0; i < 8; i++)
                #pragma unroll
                for (int j = 0; j < 8; j++)
                    acc[i][j] = fmaf(ar[i], br[j], acc[i][j]);
        }
        __syncthreads();
    }

    int crow0 = brow * 128 + ty * 8;
    int ccol0 = bcol * 128 + tx * 8;
    #pragma unroll
    for (int i = 0; i < 8; i++) {
        size_t r = crow0 + i;
        #pragma unroll
        for (int j = 0; j < 8; j++) {
            int c = ccol0 + j;
            float v = acc[i][j] + bias[c];
            if (EPI == 1) v += res[r * N + c];
            if (EPI == 2) v = 0.5f * v * (1.0f + erff(v * 0.7071067811865475f));
            C[r * N + c] = v;
        }
    }
}

// ---------------------------------------------------------------------------
// Flash attention, fp32. BQ=BKV=64, D=64. 256 threads (16x16), 4x4 per-thread
// tiles for both S=QK^T and O=PV. K-tile SMEM is reused for the P tile.
// Q is pre-scaled by 1/sqrt(D)=0.125. Online softmax with -1e30 masking.
// qstride/kstride/vstride = float stride between consecutive tokens.
// Output layout: [B*T, C] row-major, column = h*64 + d.
// ---------------------------------------------------------------------------
#define FLASH_SMEM (3 * 64 * 68 * 4)

template<bool CAUSAL>
__global__ void __launch_bounds__(256) flash_kernel(
    const float* __restrict__ Qp, const float* __restrict__ Kp,
    const float* __restrict__ Vp, float* __restrict__ Op,
    int qstride, int kstride, int vstride)
{
    int qt = blockIdx.x, h = blockIdx.y, b = blockIdx.z;
    int q0 = qt * 64;

    extern __shared__ float sm[];
    float (*Qs)[68]  = (float(*)[68])(sm);                // [d][i]
    float (*KPs)[68] = (float(*)[68])(sm + 64 * 68);      // K:[d][j]  then P:[i][j]
    float (*Vs)[68]  = (float(*)[68])(sm + 2 * 64 * 68);  // [j][d]

    int tid = threadIdx.x;
    int lr = tid >> 2, lc = tid & 3;   // load mapping: 4 threads per row
    int ty = tid >> 4, tx = tid & 15;  // compute mapping: 16x16

    const float* Qg  = Qp + (size_t)(b * T_SEQ + q0) * qstride + h * 64;
    const float* Kg0 = Kp + (size_t)(b * T_SEQ) * kstride + h * 64;
    const float* Vg0 = Vp + (size_t)(b * T_SEQ) * vstride + h * 64;

    // Load Q tile transposed into Qs[d][i], pre-scaled by 1/8
    #pragma unroll
    for (int c = 0; c < 4; c++) {
        int d0 = (lc * 4 + c) * 4;
        float4 qv = *(const float4*)(Qg + (size_t)lr * qstride + d0);
        Qs[d0 + 0][lr] = qv.x * 0.125f;
        Qs[d0 + 1][lr] = qv.y * 0.125f;
        Qs[d0 + 2][lr] = qv.z * 0.125f;
        Qs[d0 + 3][lr] = qv.w * 0.125f;
    }

    float m[4], l[4], o[4][4];
    #pragma unroll
    for (int i = 0; i < 4; i++) {
        m[i] = -1e30f; l[i] = 0.f;
        #pragma unroll
        for (int j = 0; j < 4; j++) o[i][j] = 0.f;
    }

    int ntiles = CAUSAL ? (qt + 1) : (T_SEQ / 64);
    for (int kt = 0; kt < ntiles; kt++) {
        int k0 = kt * 64;
        __syncthreads();  // previous iteration's SMEM reads done (also covers Q load)
        #pragma unroll
        for (int c = 0; c < 4; c++) {
            int d0 = (lc * 4 + c) * 4;
            float4 kv4 = *(const float4*)(Kg0 + (size_t)(k0 + lr) * kstride + d0);
            KPs[d0 + 0][lr] = kv4.x;
            KPs[d0 + 1][lr] = kv4.y;
            KPs[d0 + 2][lr] = kv4.z;
            KPs[d0 + 3][lr] = kv4.w;
            *(float4*)&Vs[lr][d0] = *(const float4*)(Vg0 + (size_t)(k0 + lr) * vstride + d0);
        }
        __syncthreads();

        // S tile = Q K^T (4x4 per thread)
        float s[4][4];
        #pragma unroll
        for (int i = 0; i < 4; i++)
            #pragma unroll
            for (int j = 0; j < 4; j++) s[i][j] = 0.f;
        #pragma unroll 8
        for (int d = 0; d < 64; d++) {
            float ar[4], br[4];
            #pragma unroll
            for (int i = 0; i < 4; i++) ar[i] = Qs[d][ty * 4 + i];
            #pragma unroll
            for (int j = 0; j < 4; j++) br[j] = KPs[d][tx * 4 + j];
            #pragma unroll
            for (int i = 0; i < 4; i++)
                #pragma unroll
                for (int j = 0; j < 4; j++)
                    s[i][j] = fmaf(ar[i], br[j], s[i][j]);
        }
        if (CAUSAL && kt == qt) {  // mask only ever needed on the diagonal tile
            #pragma unroll
            for (int i = 0; i < 4; i++) {
                int qi = q0 + ty * 4 + i;
                #pragma unroll
                for (int j = 0; j < 4; j++)
                    if (k0 + tx * 4 + j > qi) s[i][j] = -1e30f;
            }
        }
        __syncthreads();  // all threads done reading K from KPs

        // Online softmax; write P (natural [i][j]) into KPs
        #pragma unroll
        for (int i = 0; i < 4; i++) {
            float mr = fmaxf(fmaxf(s[i][0], s[i][1]), fmaxf(s[i][2], s[i][3]));
            #pragma unroll
            for (int off = 8; off; off >>= 1)
                mr = fmaxf(mr, __shfl_xor_sync(0xffffffffu, mr, off, 16));
            float mnew = fmaxf(m[i], mr);
            float corr = __expf(m[i] - mnew);
            float p0 = __expf(s[i][0] - mnew);
            float p1 = __expf(s[i][1] - mnew);
            float p2 = __expf(s[i][2] - mnew);
            float p3 = __expf(s[i][3] - mnew);
            float rs = p0 + p1 + p2 + p3;
            #pragma unroll
            for (int off = 8; off; off >>= 1)
                rs += __shfl_xor_sync(0xffffffffu, rs, off, 16);
            l[i] = l[i] * corr + rs;
            m[i] = mnew;
            #pragma unroll
            for (int d2 = 0; d2 < 4; d2++) o[i][d2] *= corr;
            *(float4*)&KPs[ty * 4 + i][tx * 4] = make_float4(p0, p1, p2, p3);
        }
        __syncthreads();

        // O += P V  (contract over j)
        #pragma unroll 4
        for (int j = 0; j < 64; j++) {
            float4 bv = *(const float4*)&Vs[j][tx * 4];
            #pragma unroll
            for (int i = 0; i < 4; i++) {
                float a = KPs[ty * 4 + i][j];
                o[i][0] = fmaf(a, bv.x, o[i][0]);
                o[i][1] = fmaf(a, bv.y, o[i][1]);
                o[i][2] = fmaf(a, bv.z, o[i][2]);
                o[i][3] = fmaf(a, bv.w, o[i][3]);
            }
        }
    }

    // Normalize and write out: [B*T, C] with col = h*64 + d
    #pragma unroll
    for (int i = 0; i < 4; i++) {
        float inv = 1.0f / l[i];
        size_t row = (size_t)(b * T_SEQ + q0 + ty * 4 + i);
        *(float4*)(Op + row * C_DIM + h * 64 + tx * 4) =
            make_float4(o[i][0] * inv, o[i][1] * inv, o[i][2] * inv, o[i][3] * inv);
    }
}

// ---------------------------------------------------------------------------
// Launch: 12 kernels, default stream, graph-capturable.
// ---------------------------------------------------------------------------
extern "C" void kernel_launch(void* const* d_in, const int* in_sizes, int n_in,
                              void* d_out, int out_size)
{
    const float* x           = (const float*)d_in[0];
    const float* context     = (const float*)d_in[1];
    const float* ln1_g       = (const float*)d_in[2];
    const float* ln1_b       = (const float*)d_in[3];
    const float* qkv_w       = (const float*)d_in[4];
    const float* qkv_b       = (const float*)d_in[5];
    const float* attn_out_w  = (const float*)d_in[6];
    const float* attn_out_b  = (const float*)d_in[7];
    const float* lnc_g       = (const float*)d_in[8];
    const float* lnc_b       = (const float*)d_in[9];
    const float* q_w         = (const float*)d_in[10];
    const float* q_b         = (const float*)d_in[11];
    const float* kv_w        = (const float*)d_in[12];
    const float* kv_b        = (const float*)d_in[13];
    const float* cross_out_w = (const float*)d_in[14];
    const float* cross_out_b = (const float*)d_in[15];
    const float* ln2_g       = (const float*)d_in[16];
    const float* ln2_b       = (const float*)d_in[17];
    const float* ffn_w1      = (const float*)d_in[18];
    const float* ffn_b1      = (const float*)d_in[19];
    const float* ffn_w2      = (const float*)d_in[20];
    const float* ffn_b2      = (const float*)d_in[21];
    float* out = (float*)d_out;

    float *h, *qkv, *attn, *x1, *x2, *q2, *kv, *ffn;
    cudaGetSymbolAddress((void**)&h,    g_h);
    cudaGetSymbolAddress((void**)&qkv,  g_qkv);
    cudaGetSymbolAddress((void**)&attn, g_attn);
    cudaGetSymbolAddress((void**)&x1,   g_x1);
    cudaGetSymbolAddress((void**)&x2,   g_x2);
    cudaGetSymbolAddress((void**)&q2,   g_q2);
    cudaGetSymbolAddress((void**)&kv,   g_kv);
    cudaGetSymbolAddress((void**)&ffn,  g_ffn);

    cudaFuncSetAttribute(flash_kernel<true>,
                         cudaFuncAttributeMaxDynamicSharedMemorySize, FLASH_SMEM);
    cudaFuncSetAttribute(flash_kernel<false>,
                         cudaFuncAttributeMaxDynamicSharedMemorySize, FLASH_SMEM);

    const int M = M_ROWS;
    dim3 fgrid(T_SEQ / 64, H_HEADS, 4);

    // 1) h = LN1(x)
    ln_kernel<<<M, 256>>>(x, ln1_g, ln1_b, h);
    // 2) qkv = h @ qkv_w + qkv_b
    sgemm_kernel<0><<<dim3(3 * C_DIM / 128, M / 128), 256>>>(
        h, qkv_w, qkv_b, nullptr, qkv, M, 3 * C_DIM, C_DIM);
    // 3) self-attention (causal) -> attn
    flash_kernel<true><<<fgrid, 256, FLASH_SMEM>>>(
        qkv, qkv + C_DIM, qkv + 2 * C_DIM, attn, 3 * C_DIM, 3 * C_DIM, 3 * C_DIM);
    // 4) x1 = x + attn @ attn_out_w + attn_out_b
    sgemm_kernel<1><<<dim3(C_DIM / 128, M / 128), 256>>>(
        attn, attn_out_w, attn_out_b, x, x1, M, C_DIM, C_DIM);
    // 5) h = LNc(x1)
    ln_kernel<<<M, 256>>>(x1, lnc_g, lnc_b, h);
    // 6) q2 = h @ q_w + q_b
    sgemm_kernel<0><<<dim3(C_DIM / 128, M / 128), 256>>>(
        h, q_w, q_b, nullptr, q2, M, C_DIM, C_DIM);
    // 7) kv = context @ kv_w + kv_b
    sgemm_kernel<0><<<dim3(2 * C_DIM / 128, M / 128), 256>>>(
        context, kv_w, kv_b, nullptr, kv, M, 2 * C_DIM, C_DIM);
    // 8) cross-attention (no mask) -> attn
    flash_kernel<false><<<fgrid, 256, FLASH_SMEM>>>(
        q2, kv, kv + C_DIM, attn, C_DIM, 2 * C_DIM, 2 * C_DIM);
    // 9) x2 = x1 + attn @ cross_out_w + cross_out_b
    sgemm_kernel<1><<<dim3(C_DIM / 128, M / 128), 256>>>(
        attn, cross_out_w, cross_out_b, x1, x2, M, C_DIM, C_DIM);
    // 10) h = LN2(x2)
    ln_kernel<<<M, 256>>>(x2, ln2_g, ln2_b, h);
    // 11) ffn = gelu(h @ ffn_w1 + ffn_b1)
    sgemm_kernel<2><<<dim3(F_DIM / 128, M / 128), 256>>>(
        h, ffn_w1, ffn_b1, nullptr, ffn, M, F_DIM, C_DIM);
    // 12) out = x2 + ffn @ ffn_w2 + ffn_b2
    sgemm_kernel<1><<<dim3(C_DIM / 128, M / 128), 256>>>(
        ffn, ffn_w2, ffn_b2, x2, out, M, C_DIM, F_DIM);
}

// round 2
// speedup vs baseline: 1.6481x; 1.6481x over previous
#include <cuda_runtime.h>
#include <cuda_bf16.h>
#include <cstdint>
#include <math.h>

typedef __nv_bfloat16 bf16;

// ---------------------------------------------------------------------------
// Problem constants: B=4, T=1024, C=1024, H=16, D=64, F=4096, M=B*T=4096
// ---------------------------------------------------------------------------
#define M_ROWS 4096
#define C_DIM  1024
#define T_SEQ  1024
#define H_HEADS 16
#define F_DIM  4096

// ---------------------------------------------------------------------------
// Scratch (device globals — allocation-free per harness rules)
// bf16 "triple" arrays hold the 3-way split along K: A-pattern (hi,hi,lo),
// B-pattern rows (hi,lo,hi), so a single K'=3K bf16 GEMM computes
// Ah*Bh + Ah*Bl + Al*Bh  (~1e-5 relative accuracy, fp32 accumulate).
// ---------------------------------------------------------------------------
__device__ float g_qkv[M_ROWS * 3 * C_DIM];
__device__ float g_x1 [M_ROWS * C_DIM];
__device__ float g_x2 [M_ROWS * C_DIM];
__device__ float g_q2f[M_ROWS * C_DIM];
__device__ float g_kvf[M_ROWS * 2 * C_DIM];

__device__ bf16 g_h2   [M_ROWS * 3 * C_DIM];          // LN outputs (triple)
__device__ bf16 g_attn2[M_ROWS * 3 * C_DIM];          // attention out (triple)
__device__ bf16 g_ctx2 [M_ROWS * 3 * C_DIM];          // context (triple)
__device__ bf16 g_ffn2a[(size_t)M_ROWS * 3 * F_DIM];  // gelu(ffn1) (triple)

__device__ bf16 w_qkv2[3 * C_DIM * 3 * C_DIM];
__device__ bf16 w_ao2 [3 * C_DIM * C_DIM];
__device__ bf16 w_q2  [3 * C_DIM * C_DIM];
__device__ bf16 w_kv2 [3 * C_DIM * 2 * C_DIM];
__device__ bf16 w_co2 [3 * C_DIM * C_DIM];
__device__ bf16 w_f1_2[3 * C_DIM * F_DIM];
__device__ bf16 w_f2_2[(size_t)3 * F_DIM * C_DIM];

// ---------------------------------------------------------------------------
// Split helpers
// ---------------------------------------------------------------------------
__device__ __forceinline__ void split_bf16(float x, bf16& hi, bf16& lo) {
    hi = __float2bfloat16(x);
    lo = __float2bfloat16(x - __bfloat162float(hi));
}

// Weight conversion: src [K][N] fp32 -> dst [3K][N] bf16 rows (hi, lo, hi)
__global__ void convB_kernel(const float* __restrict__ src, bf16* __restrict__ dst,
                             int K, int N) {
    int e = blockIdx.x * 256 + threadIdx.x;
    if (e >= K * N) return;
    int k = e / N, n = e % N;
    bf16 hi, lo; split_bf16(src[e], hi, lo);
    size_t o = (size_t)(3 * k) * N + n;
    dst[o] = hi; dst[o + N] = lo; dst[o + 2 * N] = hi;
}

// Activation conversion: src [M][K] fp32 -> dst [M][3K] bf16 cols (hi, hi, lo)
__global__ void convA_kernel(const float* __restrict__ src, bf16* __restrict__ dst,
                             int K, int total) {
    int e = blockIdx.x * 256 + threadIdx.x;
    if (e >= total) return;
    int m = e / K, k = e % K;
    bf16 hi, lo; split_bf16(src[e], hi, lo);
    size_t o = (size_t)m * 3 * K + 3 * k;
    dst[o] = hi; dst[o + 1] = hi; dst[o + 2] = lo;
}

// ---------------------------------------------------------------------------
// LayerNorm over C=1024, one block per row, 256 threads x float4.
// Writes the bf16 triple directly (output only ever feeds a GEMM A operand).
// ---------------------------------------------------------------------------
__global__ void __launch_bounds__(256) ln_kernel(
    const float* __restrict__ x, const float* __restrict__ g,
    const float* __restrict__ b, bf16* __restrict__ out)
{
    int row = blockIdx.x;
    int tid = threadIdx.x;
    float4 v = ((const float4*)(x + (size_t)row * C_DIM))[tid];
    float s  = v.x + v.y + v.z + v.w;
    float s2 = v.x*v.x + v.y*v.y + v.z*v.z + v.w*v.w;
    __shared__ float red[64];
    #pragma unroll
    for (int o = 16; o; o >>= 1) {
        s  += __shfl_xor_sync(0xffffffffu, s,  o);
        s2 += __shfl_xor_sync(0xffffffffu, s2, o);
    }
    int warp = tid >> 5;
    if ((tid & 31) == 0) { red[warp] = s; red[32 + warp] = s2; }
    __syncthreads();
    if (tid < 32) {
        s  = (tid < 8) ? red[tid]      : 0.f;
        s2 = (tid < 8) ? red[32 + tid] : 0.f;
        #pragma unroll
        for (int o = 4; o; o >>= 1) {
            s  += __shfl_xor_sync(0xffffffffu, s,  o);
            s2 += __shfl_xor_sync(0xffffffffu, s2, o);
        }
        if (tid == 0) { red[0] = s; red[32] = s2; }
    }
    __syncthreads();
    float mean = red[0]  * (1.0f / C_DIM);
    float var  = red[32] * (1.0f / C_DIM) - mean * mean;
    float inv  = rsqrtf(var + 1e-5f);
    float4 gv = ((const float4*)g)[tid];
    float4 bv = ((const float4*)b)[tid];
    float ov[4];
    ov[0] = (v.x - mean) * inv * gv.x + bv.x;
    ov[1] = (v.y - mean) * inv * gv.y + bv.y;
    ov[2] = (v.z - mean) * inv * gv.z + bv.z;
    ov[3] = (v.w - mean) * inv * gv.w + bv.w;
    bf16* o = out + (size_t)row * 3 * C_DIM + 12 * tid;
    #pragma unroll
    for (int j = 0; j < 4; j++) {
        bf16 hi, lo; split_bf16(ov[j], hi, lo);
        o[3*j] = hi; o[3*j+1] = hi; o[3*j+2] = lo;
    }
}

// ---------------------------------------------------------------------------
// bf16 tensor-core GEMM:  C[M,N] = A[M,Kp](bf16) @ B[Kp,N](bf16) + bias ...
// BM=BN=128, BK=32, 256 threads (8 warps, 2x4), 3-stage cp.async pipeline,
// ldmatrix + mma.sync.m16n8k16 (fp32 accumulate).
// EPI: 0 = +bias (fp32 out), 1 = +bias+res (fp32 out),
//      3 = +bias, exact GELU, emit bf16 triple (A-pattern) for next GEMM.
// ---------------------------------------------------------------------------
#define BM 128
#define BN 128
#define BK 32
#define A_PAD 40    // bf16 elems per A smem row (80 B)
#define B_PAD 136   // bf16 elems per B smem row (272 B)
#define BG_SMEM (3 * (BM * A_PAD + BK * B_PAD) * 2)   // 56832 B

__device__ __forceinline__ void cp16(uint32_t dst, const void* src) {
    asm volatile("cp.async.cg.shared.global [%0], [%1], 16;\n" :: "r"(dst), "l"(src));
}
__device__ __forceinline__ void ldm_x4(uint32_t& r0, uint32_t& r1, uint32_t& r2,
                                       uint32_t& r3, uint32_t addr) {
    asm volatile("ldmatrix.sync.aligned.m8n8.x4.shared.b16 {%0,%1,%2,%3}, [%4];\n"
        : "=r"(r0), "=r"(r1), "=r"(r2), "=r"(r3) : "r"(addr));
}
__device__ __forceinline__ void ldm_x4_t(uint32_t& r0, uint32_t& r1, uint32_t& r2,
                                         uint32_t& r3, uint32_t addr) {
    asm volatile("ldmatrix.sync.aligned.m8n8.x4.trans.shared.b16 {%0,%1,%2,%3}, [%4];\n"
        : "=r"(r0), "=r"(r1), "=r"(r2), "=r"(r3) : "r"(addr));
}
__device__ __forceinline__ void mma_bf16(float* d, const uint32_t* a, const uint32_t* b) {
    asm volatile("mma.sync.aligned.m16n8k16.row.col.f32.bf16.bf16.f32 "
        "{%0,%1,%2,%3}, {%4,%5,%6,%7}, {%8,%9}, {%0,%1,%2,%3};\n"
        : "+f"(d[0]), "+f"(d[1]), "+f"(d[2]), "+f"(d[3])
        : "r"(a[0]), "r"(a[1]), "r"(a[2]), "r"(a[3]), "r"(b[0]), "r"(b[1]));
}

template<int EPI>
__global__ void __launch_bounds__(256, 2) bgemm_kernel(
    const bf16* __restrict__ A, const bf16* __restrict__ Bm,
    const float* __restrict__ bias, const float* __restrict__ res,
    float* __restrict__ Cf, bf16* __restrict__ Ct, int M, int N, int Kp)
{
    extern __shared__ char sm_raw[];
    bf16* As = (bf16*)sm_raw;                                   // [3][BM][A_PAD]
    bf16* Bs = (bf16*)(sm_raw + 3 * BM * A_PAD * sizeof(bf16)); // [3][BK][B_PAD]

    const int tid  = threadIdx.x;
    const int lane = tid & 31, wid = tid >> 5;
    const int bm0 = blockIdx.y * BM, bn0 = blockIdx.x * BN;
    const int wm = (wid >> 2) * 64, wn = (wid & 3) * 32;

    const int arow = tid >> 2, ac8 = (tid & 3) * 8;
    const int brow = tid >> 4, bc8 = (tid & 15) * 8;

    float acc[4][4][4];
    #pragma unroll
    for (int i = 0; i < 4; i++)
        #pragma unroll
        for (int j = 0; j < 4; j++)
            #pragma unroll
            for (int r = 0; r < 4; r++) acc[i][j][r] = 0.f;

    auto As_u32 = [&](int s, int r, int c) -> uint32_t {
        return (uint32_t)__cvta_generic_to_shared(As + ((s * BM + r) * A_PAD + c));
    };
    auto Bs_u32 = [&](int s, int r, int c) -> uint32_t {
        return (uint32_t)__cvta_generic_to_shared(Bs + ((s * BK + r) * B_PAD + c));
    };

    auto load_stage = [&](int s, int k0) {
        #pragma unroll
        for (int i = 0; i < 2; i++) {
            cp16(As_u32(s, arow + i * 64, ac8),
                 A + (size_t)(bm0 + arow + i * 64) * Kp + k0 + ac8);
            cp16(Bs_u32(s, brow + i * 16, bc8),
                 Bm + (size_t)(k0 + brow + i * 16) * N + bn0 + bc8);
        }
        asm volatile("cp.async.commit_group;\n" ::);
    };

    load_stage(0, 0);
    load_stage(1, BK);
    const int NK = Kp / BK;

    for (int t = 0; t < NK; t++) {
        asm volatile("cp.async.wait_group 1;\n" ::);
        __syncthreads();
        if (t + 2 < NK) load_stage((t + 2) % 3, (t + 2) * BK);
        const int s = t % 3;

        #pragma unroll
        for (int k16 = 0; k16 < 2; k16++) {
            uint32_t af[4][4];
            #pragma unroll
            for (int mi = 0; mi < 4; mi++) {
                uint32_t addr = As_u32(s, wm + mi * 16 + (lane & 15),
                                       k16 * 16 + ((lane >> 4) << 3));
                ldm_x4(af[mi][0], af[mi][1], af[mi][2], af[mi][3], addr);
            }
            uint32_t bfr[4][2];
            #pragma unroll
            for (int njp = 0; njp < 2; njp++) {
                int kr = k16 * 16 + ((lane >> 3) & 1) * 8 + (lane & 7);
                int nc = wn + njp * 16 + ((lane >> 4) & 1) * 8;
                uint32_t r0, r1, r2, r3;
                ldm_x4_t(r0, r1, r2, r3, Bs_u32(s, kr, nc));
                bfr[2*njp][0] = r0; bfr[2*njp][1] = r1;
                bfr[2*njp+1][0] = r2; bfr[2*njp+1][1] = r3;
            }
            #pragma unroll
            for (int mi = 0; mi < 4; mi++)
                #pragma unroll
                for (int nj = 0; nj < 4; nj++)
                    mma_bf16(acc[mi][nj], af[mi], bfr[nj]);
        }
    }

    // Epilogue
    const int g = lane >> 2, tig = lane & 3;
    #pragma unroll
    for (int mi = 0; mi < 4; mi++) {
        #pragma unroll
        for (int r2 = 0; r2 < 2; r2++) {
            int row = bm0 + wm + mi * 16 + g + r2 * 8;
            #pragma unroll
            for (int nj = 0; nj < 4; nj++) {
                int col = bn0 + wn + nj * 8 + tig * 2;
                float v0 = acc[mi][nj][r2 * 2 + 0] + bias[col];
                float v1 = acc[mi][nj][r2 * 2 + 1] + bias[col + 1];
                if (EPI == 1) {
                    float2 rv = *(const float2*)(res + (size_t)row * N + col);
                    v0 += rv.x; v1 += rv.y;
                }
                if (EPI == 3) {
                    v0 = 0.5f * v0 * (1.0f + erff(v0 * 0.7071067811865475f));
                    v1 = 0.5f * v1 * (1.0f + erff(v1 * 0.7071067811865475f));
                    bf16 h0, l0, h1, l1;
                    split_bf16(v0, h0, l0);
                    split_bf16(v1, h1, l1);
                    size_t o = (size_t)row * 3 * N + 3 * col;
                    Ct[o]   = h0; Ct[o+1] = h0; Ct[o+2] = l0;
                    Ct[o+3] = h1; Ct[o+4] = h1; Ct[o+5] = l1;
                } else {
                    *(float2*)(Cf + (size_t)row * N + col) = make_float2(v0, v1);
                }
            }
        }
    }
}

// ---------------------------------------------------------------------------
// Flash attention, fp32 SIMT (unchanged math). Output written as bf16 triple
// (it only ever feeds a GEMM A operand).
// ---------------------------------------------------------------------------
#define FLASH_SMEM (3 * 64 * 68 * 4)

template<bool CAUSAL>
__global__ void __launch_bounds__(256) flash_kernel(
    const float* __restrict__ Qp, const float* __restrict__ Kp,
    const float* __restrict__ Vp, bf16* __restrict__ Op,
    int qstride, int kstride, int vstride)
{
    int qt = blockIdx.x, h = blockIdx.y, b = blockIdx.z;
    int q0 = qt * 64;

    extern __shared__ float sm[];
    float (*Qs)[68]  = (float(*)[68])(sm);
    float (*KPs)[68] = (float(*)[68])(sm + 64 * 68);
    float (*Vs)[68]  = (float(*)[68])(sm + 2 * 64 * 68);

    int tid = threadIdx.x;
    int lr = tid >> 2, lc = tid & 3;
    int ty = tid >> 4, tx = tid & 15;

    const float* Qg  = Qp + (size_t)(b * T_SEQ + q0) * qstride + h * 64;
    const float* Kg0 = Kp + (size_t)(b * T_SEQ) * kstride + h * 64;
    const float* Vg0 = Vp + (size_t)(b * T_SEQ) * vstride + h * 64;

    #pragma unroll
    for (int c = 0; c < 4; c++) {
        int d0 = (lc * 4 + c) * 4;
        float4 qv = *(const float4*)(Qg + (size_t)lr * qstride + d0);
        Qs[d0 + 0][lr] = qv.x * 0.125f;
        Qs[d0 + 1][lr] = qv.y * 0.125f;
        Qs[d0 + 2][lr] = qv.z * 0.125f;
        Qs[d0 + 3][lr] = qv.w * 0.125f;
    }

    float m[4], l[4], o[4][4];
    #pragma unroll
    for (int i = 0; i < 4; i++) {
        m[i] = -1e30f; l[i] = 0.f;
        #pragma unroll
        for (int j = 0; j < 4; j++) o[i][j] = 0.f;
    }

    int ntiles = CAUSAL ? (qt + 1) : (T_SEQ / 64);
    for (int kt = 0; kt < ntiles; kt++) {
        int k0 = kt * 64;
        __syncthreads();
        #pragma unroll
        for (int c = 0; c < 4; c++) {
            int d0 = (lc * 4 + c) * 4;
            float4 kv4 = *(const float4*)(Kg0 + (size_t)(k0 + lr) * kstride + d0);
            KPs[d0 + 0][lr] = kv4.x;
            KPs[d0 + 1][lr] = kv4.y;
            KPs[d0 + 2][lr] = kv4.z;
            KPs[d0 + 3][lr] = kv4.w;
            *(float4*)&Vs[lr][d0] = *(const float4*)(Vg0 + (size_t)(k0 + lr) * vstride + d0);
        }
        __syncthreads();

        float s[4][4];
        #pragma unroll
        for (int i = 0; i < 4; i++)
            #pragma unroll
            for (int j = 0; j < 4; j++) s[i][j] = 0.f;
        #pragma unroll 8
        for (int d = 0; d < 64; d++) {
            float ar[4], br[4];
            #pragma unroll
            for (int i = 0; i < 4; i++) ar[i] = Qs[d][ty * 4 + i];
            #pragma unroll
            for (int j = 0; j < 4; j++) br[j] = KPs[d][tx * 4 + j];
            #pragma unroll
            for (int i = 0; i < 4; i++)
                #pragma unroll
                for (int j = 0; j < 4; j++)
                    s[i][j] = fmaf(ar[i], br[j], s[i][j]);
        }
        if (CAUSAL && kt == qt) {
            #pragma unroll
            for (int i = 0; i < 4; i++) {
                int qi = q0 + ty * 4 + i;
                #pragma unroll
                for (int j = 0; j < 4; j++)
                    if (k0 + tx * 4 + j > qi) s[i][j] = -1e30f;
            }
        }
        __syncthreads();

        #pragma unroll
        for (int i = 0; i < 4; i++) {
            float mr = fmaxf(fmaxf(s[i][0], s[i][1]), fmaxf(s[i][2], s[i][3]));
            #pragma unroll
            for (int off = 8; off; off >>= 1)
                mr = fmaxf(mr, __shfl_xor_sync(0xffffffffu, mr, off, 16));
            float mnew = fmaxf(m[i], mr);
            float corr = __expf(m[i] - mnew);
            float p0 = __expf(s[i][0] - mnew);
            float p1 = __expf(s[i][1] - mnew);
            float p2 = __expf(s[i][2] - mnew);
            float p3 = __expf(s[i][3] - mnew);
            float rs = p0 + p1 + p2 + p3;
            #pragma unroll
            for (int off = 8; off; off >>= 1)
                rs += __shfl_xor_sync(0xffffffffu, rs, off, 16);
            l[i] = l[i] * corr + rs;
            m[i] = mnew;
            #pragma unroll
            for (int d2 = 0; d2 < 4; d2++) o[i][d2] *= corr;
            *(float4*)&KPs[ty * 4 + i][tx * 4] = make_float4(p0, p1, p2, p3);
        }
        __syncthreads();

        #pragma unroll 4
        for (int j = 0; j < 64; j++) {
            float4 bv = *(const float4*)&Vs[j][tx * 4];
            #pragma unroll
            for (int i = 0; i < 4; i++) {
                float a = KPs[ty * 4 + i][j];
                o[i][0] = fmaf(a, bv.x, o[i][0]);
                o[i][1] = fmaf(a, bv.y, o[i][1]);
                o[i][2] = fmaf(a, bv.z, o[i][2]);
                o[i][3] = fmaf(a, bv.w, o[i][3]);
            }
        }
    }

    #pragma unroll
    for (int i = 0; i < 4; i++) {
        float inv = 1.0f / l[i];
        size_t row = (size_t)(b * T_SEQ + q0 + ty * 4 + i);
        bf16* ob = Op + row * 3 * C_DIM + 3 * (h * 64 + tx * 4);
        #pragma unroll
        for (int j = 0; j < 4; j++) {
            bf16 hi, lo; split_bf16(o[i][j] * inv, hi, lo);
            ob[3*j] = hi; ob[3*j+1] = hi; ob[3*j+2] = lo;
        }
    }
}

// ---------------------------------------------------------------------------
// Launch
// ---------------------------------------------------------------------------
static inline int cdiv(int a, int b) { return (a + b - 1) / b; }

extern "C" void kernel_launch(void* const* d_in, const int* in_sizes, int n_in,
                              void* d_out, int out_size)
{
    const float* x           = (const float*)d_in[0];
    const float* context     = (const float*)d_in[1];
    const float* ln1_g       = (const float*)d_in[2];
    const float* ln1_b       = (const float*)d_in[3];
    const float* qkv_w       = (const float*)d_in[4];
    const float* qkv_b       = (const float*)d_in[5];
    const float* attn_out_w  = (const float*)d_in[6];
    const float* attn_out_b  = (const float*)d_in[7];
    const float* lnc_g       = (const float*)d_in[8];
    const float* lnc_b       = (const float*)d_in[9];
    const float* q_w         = (const float*)d_in[10];
    const float* q_b         = (const float*)d_in[11];
    const float* kv_w        = (const float*)d_in[12];
    const float* kv_b        = (const float*)d_in[13];
    const float* cross_out_w = (const float*)d_in[14];
    const float* cross_out_b = (const float*)d_in[15];
    const float* ln2_g       = (const float*)d_in[16];
    const float* ln2_b       = (const float*)d_in[17];
    const float* ffn_w1      = (const float*)d_in[18];
    const float* ffn_b1      = (const float*)d_in[19];
    const float* ffn_w2      = (const float*)d_in[20];
    const float* ffn_b2      = (const float*)d_in[21];
    float* out = (float*)d_out;

    float *qkv, *x1, *x2, *q2f, *kvf;
    bf16 *h2, *attn2, *ctx2, *ffn2a;
    bf16 *wqkv2, *wao2, *wq2, *wkv2, *wco2, *wf1, *wf2;
    cudaGetSymbolAddress((void**)&qkv,   g_qkv);
    cudaGetSymbolAddress((void**)&x1,    g_x1);
    cudaGetSymbolAddress((void**)&x2,    g_x2);
    cudaGetSymbolAddress((void**)&q2f,   g_q2f);
    cudaGetSymbolAddress((void**)&kvf,   g_kvf);
    cudaGetSymbolAddress((void**)&h2,    g_h2);
    cudaGetSymbolAddress((void**)&attn2, g_attn2);
    cudaGetSymbolAddress((void**)&ctx2,  g_ctx2);
    cudaGetSymbolAddress((void**)&ffn2a, g_ffn2a);
    cudaGetSymbolAddress((void**)&wqkv2, w_qkv2);
    cudaGetSymbolAddress((void**)&wao2,  w_ao2);
    cudaGetSymbolAddress((void**)&wq2,   w_q2);
    cudaGetSymbolAddress((void**)&wkv2,  w_kv2);
    cudaGetSymbolAddress((void**)&wco2,  w_co2);
    cudaGetSymbolAddress((void**)&wf1,   w_f1_2);
    cudaGetSymbolAddress((void**)&wf2,   w_f2_2);

    cudaFuncSetAttribute(bgemm_kernel<0>, cudaFuncAttributeMaxDynamicSharedMemorySize, BG_SMEM);
    cudaFuncSetAttribute(bgemm_kernel<1>, cudaFuncAttributeMaxDynamicSharedMemorySize, BG_SMEM);
    cudaFuncSetAttribute(bgemm_kernel<3>, cudaFuncAttributeMaxDynamicSharedMemorySize, BG_SMEM);
    cudaFuncSetAttribute(flash_kernel<true>,  cudaFuncAttributeMaxDynamicSharedMemorySize, FLASH_SMEM);
    cudaFuncSetAttribute(flash_kernel<false>, cudaFuncAttributeMaxDynamicSharedMemorySize, FLASH_SMEM);

    const int M = M_ROWS, C = C_DIM, F = F_DIM;
    dim3 fgrid(T_SEQ / 64, H_HEADS, 4);

    // Weight + context splits (recomputed each call — deterministic, ~100 MB traffic)
    convB_kernel<<<cdiv(C * 3 * C, 256), 256>>>(qkv_w,       wqkv2, C, 3 * C);
    convB_kernel<<<cdiv(C * C,     256), 256>>>(attn_out_w,  wao2,  C, C);
    convB_kernel<<<cdiv(C * C,     256), 256>>>(q_w,         wq2,   C, C);
    convB_kernel<<<cdiv(C * 2 * C, 256), 256>>>(kv_w,        wkv2,  C, 2 * C);
    convB_kernel<<<cdiv(C * C,     256), 256>>>(cross_out_w, wco2,  C, C);
    convB_kernel<<<cdiv(C * F,     256), 256>>>(ffn_w1,      wf1,   C, F);
    convB_kernel<<<cdiv(F * C,     256), 256>>>(ffn_w2,      wf2,   F, C);
    convA_kernel<<<cdiv(M * C,     256), 256>>>(context,     ctx2,  C, M * C);

    // 1) h2 = LN1(x)
    ln_kernel<<<M, 256>>>(x, ln1_g, ln1_b, h2);
    // 2) qkv = h @ qkv_w + qkv_b
    bgemm_kernel<0><<<dim3(3 * C / BN, M / BM), 256, BG_SMEM>>>(
        h2, wqkv2, qkv_b, nullptr, qkv, nullptr, M, 3 * C, 3 * C);
    // 3) self-attention (causal) -> attn2
    flash_kernel<true><<<fgrid, 256, FLASH_SMEM>>>(
        qkv, qkv + C, qkv + 2 * C, attn2, 3 * C, 3 * C, 3 * C);
    // 4) x1 = x + attn @ attn_out_w + attn_out_b
    bgemm_kernel<1><<<dim3(C / BN, M / BM), 256, BG_SMEM>>>(
        attn2, wao2, attn_out_b, x, x1, nullptr, M, C, 3 * C);
    // 5) h2 = LNc(x1)
    ln_kernel<<<M, 256>>>(x1, lnc_g, lnc_b, h2);
    // 6) q2 = h @ q_w + q_b
    bgemm_kernel<0><<<dim3(C / BN, M / BM), 256, BG_SMEM>>>(
        h2, wq2, q_b, nullptr, q2f, nullptr, M, C, 3 * C);
    // 7) kv = context @ kv_w + kv_b
    bgemm_kernel<0><<<dim3(2 * C / BN, M / BM), 256, BG_SMEM>>>(
        ctx2, wkv2, kv_b, nullptr, kvf, nullptr, M, 2 * C, 3 * C);
    // 8) cross-attention -> attn2
    flash_kernel<false><<<fgrid, 256, FLASH_SMEM>>>(
        q2f, kvf, kvf + C, attn2, C, 2 * C, 2 * C);
    // 9) x2 = x1 + attn @ cross_out_w + cross_out_b
    bgemm_kernel<1><<<dim3(C / BN, M / BM), 256, BG_SMEM>>>(
        attn2, wco2, cross_out_b, x1, x2, nullptr, M, C, 3 * C);
    // 10) h2 = LN2(x2)
    ln_kernel<<<M, 256>>>(x2, ln2_g, ln2_b, h2);
    // 11) ffn2a = triple(gelu(h @ ffn_w1 + ffn_b1))
    bgemm_kernel<3><<<dim3(F / BN, M / BM), 256, BG_SMEM>>>(
        h2, wf1, ffn_b1, nullptr, nullptr, ffn2a, M, F, 3 * C);
    // 12) out = x2 + ffn @ ffn_w2 + ffn_b2
    bgemm_kernel<1><<<dim3(C / BN, M / BM), 256, BG_SMEM>>>(
        ffn2a, wf2, ffn_b2, x2, out, nullptr, M, C, 3 * F);
}

// round 3
// speedup vs baseline: 2.0959x; 1.2717x over previous
#include <cuda_runtime.h>
#include <cuda_bf16.h>
#include <cuda_fp16.h>
#include <cstdint>
#include <math.h>

typedef __nv_bfloat16 bf16;

// ---------------------------------------------------------------------------
// Problem constants: B=4, T=1024, C=1024, H=16, D=64, F=4096, M=B*T=4096
// ---------------------------------------------------------------------------
#define M_ROWS 4096
#define C_DIM  1024
#define T_SEQ  1024
#define H_HEADS 16
#define F_DIM  4096
#define L2E 1.4426950408889634f

// ---------------------------------------------------------------------------
// Scratch (device globals)
// ---------------------------------------------------------------------------
__device__ float g_qkv[M_ROWS * 3 * C_DIM];
__device__ float g_x1 [M_ROWS * C_DIM];
__device__ float g_x2 [M_ROWS * C_DIM];
__device__ float g_q2f[M_ROWS * C_DIM];
__device__ float g_kvf[M_ROWS * 2 * C_DIM];

__device__ bf16 g_h2   [M_ROWS * 3 * C_DIM];
__device__ bf16 g_attn2[M_ROWS * 3 * C_DIM];
__device__ bf16 g_ctx2 [M_ROWS * 3 * C_DIM];
__device__ bf16 g_ffn2a[(size_t)M_ROWS * 3 * F_DIM];

__device__ bf16 w_qkv2[3 * C_DIM * 3 * C_DIM];
__device__ bf16 w_ao2 [3 * C_DIM * C_DIM];
__device__ bf16 w_q2  [3 * C_DIM * C_DIM];
__device__ bf16 w_kv2 [3 * C_DIM * 2 * C_DIM];
__device__ bf16 w_co2 [3 * C_DIM * C_DIM];
__device__ bf16 w_f1_2[3 * C_DIM * F_DIM];
__device__ bf16 w_f2_2[(size_t)3 * F_DIM * C_DIM];

// Attention operand buffers (f16 hi/lo), shared by self- and cross-attention.
#define ATT_ELEMS (4 * H_HEADS * T_SEQ * 64)   // 4M
__device__ __half a_qh[ATT_ELEMS];
__device__ __half a_ql[ATT_ELEMS];
__device__ __half a_kth[ATT_ELEMS];   // K^T: [b,h,d,t]
__device__ __half a_ktl[ATT_ELEMS];
__device__ __half a_vh[ATT_ELEMS];    // V:   [b,h,t,d]
__device__ __half a_vl[ATT_ELEMS];

// ---------------------------------------------------------------------------
// Split helpers
// ---------------------------------------------------------------------------
__device__ __forceinline__ void split_bf16(float x, bf16& hi, bf16& lo) {
    hi = __float2bfloat16(x);
    lo = __float2bfloat16(x - __bfloat162float(hi));
}

__global__ void convB_kernel(const float* __restrict__ src, bf16* __restrict__ dst,
                             int K, int N) {
    int e = blockIdx.x * 256 + threadIdx.x;
    if (e >= K * N) return;
    int k = e / N, n = e % N;
    bf16 hi, lo; split_bf16(src[e], hi, lo);
    size_t o = (size_t)(3 * k) * N + n;
    dst[o] = hi; dst[o + N] = lo; dst[o + 2 * N] = hi;
}

__global__ void convA_kernel(const float* __restrict__ src, bf16* __restrict__ dst,
                             int K, int total) {
    int e = blockIdx.x * 256 + threadIdx.x;
    if (e >= total) return;
    int m = e / K, k = e % K;
    bf16 hi, lo; split_bf16(src[e], hi, lo);
    size_t o = (size_t)m * 3 * K + 3 * k;
    dst[o] = hi; dst[o + 1] = hi; dst[o + 2] = lo;
}

// ---------------------------------------------------------------------------
// Attention pre-split kernels.
// prep_rm: out[(b*16+h)*1024 + t][d] = split_f16(in[(b*1024+t)*rowstride + coloff + h*64 + d] * scale)
// prep_tr: out[((b*16+h)*64 + d)][t] = split_f16(in[...])   (K transposed)
// ---------------------------------------------------------------------------
__global__ void prep_rm(const float* __restrict__ in, int rowstride, int coloff,
                        float scale, __half* __restrict__ oh, __half* __restrict__ ol) {
    int idx = blockIdx.x * 256 + threadIdx.x;
    if (idx >= ATT_ELEMS) return;
    int d = idx & 63;
    int t = (idx >> 6) & 1023;
    int h = (idx >> 16) & 15;
    int b = idx >> 20;
    float v = in[(size_t)(b * 1024 + t) * rowstride + coloff + h * 64 + d] * scale;
    __half hi = __float2half_rn(v);
    __half lo = __float2half_rn(v - __half2float(hi));
    size_t o = ((size_t)((b * 16 + h) * 1024) + t) * 64 + d;
    oh[o] = hi; ol[o] = lo;
}

__global__ void prep_tr(const float* __restrict__ in, int rowstride, int coloff,
                        __half* __restrict__ oh, __half* __restrict__ ol) {
    int idx = blockIdx.x * 256 + threadIdx.x;
    if (idx >= ATT_ELEMS) return;
    int t = idx & 1023;
    int d = (idx >> 10) & 63;
    int h = (idx >> 16) & 15;
    int b = idx >> 20;
    float v = in[(size_t)(b * 1024 + t) * rowstride + coloff + h * 64 + d];
    __half hi = __float2half_rn(v);
    __half lo = __float2half_rn(v - __half2float(hi));
    size_t o = ((size_t)((b * 16 + h) * 64 + d)) * 1024 + t;
    oh[o] = hi; ol[o] = lo;
}

// ---------------------------------------------------------------------------
// LayerNorm (writes bf16 triple)
// ---------------------------------------------------------------------------
__global__ void __launch_bounds__(256) ln_kernel(
    const float* __restrict__ x, const float* __restrict__ g,
    const float* __restrict__ b, bf16* __restrict__ out)
{
    int row = blockIdx.x;
    int tid = threadIdx.x;
    float4 v = ((const float4*)(x + (size_t)row * C_DIM))[tid];
    float s  = v.x + v.y + v.z + v.w;
    float s2 = v.x*v.x + v.y*v.y + v.z*v.z + v.w*v.w;
    __shared__ float red[64];
    #pragma unroll
    for (int o = 16; o; o >>= 1) {
        s  += __shfl_xor_sync(0xffffffffu, s,  o);
        s2 += __shfl_xor_sync(0xffffffffu, s2, o);
    }
    int warp = tid >> 5;
    if ((tid & 31) == 0) { red[warp] = s; red[32 + warp] = s2; }
    __syncthreads();
    if (tid < 32) {
        s  = (tid < 8) ? red[tid]      : 0.f;
        s2 = (tid < 8) ? red[32 + tid] : 0.f;
        #pragma unroll
        for (int o = 4; o; o >>= 1) {
            s  += __shfl_xor_sync(0xffffffffu, s,  o);
            s2 += __shfl_xor_sync(0xffffffffu, s2, o);
        }
        if (tid == 0) { red[0] = s; red[32] = s2; }
    }
    __syncthreads();
    float mean = red[0]  * (1.0f / C_DIM);
    float var  = red[32] * (1.0f / C_DIM) - mean * mean;
    float inv  = rsqrtf(var + 1e-5f);
    float4 gv = ((const float4*)g)[tid];
    float4 bv = ((const float4*)b)[tid];
    float ov[4];
    ov[0] = (v.x - mean) * inv * gv.x + bv.x;
    ov[1] = (v.y - mean) * inv * gv.y + bv.y;
    ov[2] = (v.z - mean) * inv * gv.z + bv.z;
    ov[3] = (v.w - mean) * inv * gv.w + bv.w;
    bf16* o = out + (size_t)row * 3 * C_DIM + 12 * tid;
    #pragma unroll
    for (int j = 0; j < 4; j++) {
        bf16 hi, lo; split_bf16(ov[j], hi, lo);
        o[3*j] = hi; o[3*j+1] = hi; o[3*j+2] = lo;
    }
}

// ---------------------------------------------------------------------------
// PTX helpers
// ---------------------------------------------------------------------------
__device__ __forceinline__ void cp16(uint32_t dst, const void* src) {
    asm volatile("cp.async.cg.shared.global [%0], [%1], 16;\n" :: "r"(dst), "l"(src));
}
__device__ __forceinline__ void ldm_x4(uint32_t& r0, uint32_t& r1, uint32_t& r2,
                                       uint32_t& r3, uint32_t addr) {
    asm volatile("ldmatrix.sync.aligned.m8n8.x4.shared.b16 {%0,%1,%2,%3}, [%4];\n"
        : "=r"(r0), "=r"(r1), "=r"(r2), "=r"(r3) : "r"(addr));
}
__device__ __forceinline__ void ldm_x4_t(uint32_t& r0, uint32_t& r1, uint32_t& r2,
                                         uint32_t& r3, uint32_t addr) {
    asm volatile("ldmatrix.sync.aligned.m8n8.x4.trans.shared.b16 {%0,%1,%2,%3}, [%4];\n"
        : "=r"(r0), "=r"(r1), "=r"(r2), "=r"(r3) : "r"(addr));
}
__device__ __forceinline__ void ldm_x2_t(uint32_t& r0, uint32_t& r1, uint32_t addr) {
    asm volatile("ldmatrix.sync.aligned.m8n8.x2.trans.shared.b16 {%0,%1}, [%2];\n"
        : "=r"(r0), "=r"(r1) : "r"(addr));
}
__device__ __forceinline__ void mma_bf16(float* d, const uint32_t* a, const uint32_t* b) {
    asm volatile("mma.sync.aligned.m16n8k16.row.col.f32.bf16.bf16.f32 "
        "{%0,%1,%2,%3}, {%4,%5,%6,%7}, {%8,%9}, {%0,%1,%2,%3};\n"
        : "+f"(d[0]), "+f"(d[1]), "+f"(d[2]), "+f"(d[3])
        : "r"(a[0]), "r"(a[1]), "r"(a[2]), "r"(a[3]), "r"(b[0]), "r"(b[1]));
}
__device__ __forceinline__ void mma_f16(float* d, const uint32_t* a, const uint32_t* b) {
    asm volatile("mma.sync.aligned.m16n8k16.row.col.f32.f16.f16.f32 "
        "{%0,%1,%2,%3}, {%4,%5,%6,%7}, {%8,%9}, {%0,%1,%2,%3};\n"
        : "+f"(d[0]), "+f"(d[1]), "+f"(d[2]), "+f"(d[3])
        : "r"(a[0]), "r"(a[1]), "r"(a[2]), "r"(a[3]), "r"(b[0]), "r"(b[1]));
}
__device__ __forceinline__ uint32_t ex2_f16x2(float a, float b) {
    __half2 h = __floats2half2_rn(a, b);
    uint32_t u = *reinterpret_cast<uint32_t*>(&h);
    uint32_t r;
    asm volatile("ex2.approx.f16x2 %0, %1;\n" : "=r"(r) : "r"(u));
    return r;
}

// ---------------------------------------------------------------------------
// bf16 tensor-core GEMM (unchanged from R1)
// ---------------------------------------------------------------------------
#define BM 128
#define BN 128
#define BK 32
#define A_PAD 40
#define B_PAD 136
#define BG_SMEM (3 * (BM * A_PAD + BK * B_PAD) * 2)

template<int EPI>
__global__ void __launch_bounds__(256, 2) bgemm_kernel(
    const bf16* __restrict__ A, const bf16* __restrict__ Bm,
    const float* __restrict__ bias, const float* __restrict__ res,
    float* __restrict__ Cf, bf16* __restrict__ Ct, int M, int N, int Kp)
{
    extern __shared__ char sm_raw[];
    bf16* As = (bf16*)sm_raw;
    bf16* Bs = (bf16*)(sm_raw + 3 * BM * A_PAD * sizeof(bf16));

    const int tid  = threadIdx.x;
    const int lane = tid & 31, wid = tid >> 5;
    const int bm0 = blockIdx.y * BM, bn0 = blockIdx.x * BN;
    const int wm = (wid >> 2) * 64, wn = (wid & 3) * 32;

    const int arow = tid >> 2, ac8 = (tid & 3) * 8;
    const int brow = tid >> 4, bc8 = (tid & 15) * 8;

    float acc[4][4][4];
    #pragma unroll
    for (int i = 0; i < 4; i++)
        #pragma unroll
        for (int j = 0; j < 4; j++)
            #pragma unroll
            for (int r = 0; r < 4; r++) acc[i][j][r] = 0.f;

    auto As_u32 = [&](int s, int r, int c) -> uint32_t {
        return (uint32_t)__cvta_generic_to_shared(As + ((s * BM + r) * A_PAD + c));
    };
    auto Bs_u32 = [&](int s, int r, int c) -> uint32_t {
        return (uint32_t)__cvta_generic_to_shared(Bs + ((s * BK + r) * B_PAD + c));
    };

    auto load_stage = [&](int s, int k0) {
        #pragma unroll
        for (int i = 0; i < 2; i++) {
            cp16(As_u32(s, arow + i * 64, ac8),
                 A + (size_t)(bm0 + arow + i * 64) * Kp + k0 + ac8);
            cp16(Bs_u32(s, brow + i * 16, bc8),
                 Bm + (size_t)(k0 + brow + i * 16) * N + bn0 + bc8);
        }
        asm volatile("cp.async.commit_group;\n" ::);
    };

    load_stage(0, 0);
    load_stage(1, BK);
    const int NK = Kp / BK;

    for (int t = 0; t < NK; t++) {
        asm volatile("cp.async.wait_group 1;\n" ::);
        __syncthreads();
        if (t + 2 < NK) load_stage((t + 2) % 3, (t + 2) * BK);
        const int s = t % 3;

        #pragma unroll
        for (int k16 = 0; k16 < 2; k16++) {
            uint32_t af[4][4];
            #pragma unroll
            for (int mi = 0; mi < 4; mi++) {
                uint32_t addr = As_u32(s, wm + mi * 16 + (lane & 15),
                                       k16 * 16 + ((lane >> 4) << 3));
                ldm_x4(af[mi][0], af[mi][1], af[mi][2], af[mi][3], addr);
            }
            uint32_t bfr[4][2];
            #pragma unroll
            for (int njp = 0; njp < 2; njp++) {
                int kr = k16 * 16 + ((lane >> 3) & 1) * 8 + (lane & 7);
                int nc = wn + njp * 16 + ((lane >> 4) & 1) * 8;
                uint32_t r0, r1, r2, r3;
                ldm_x4_t(r0, r1, r2, r3, Bs_u32(s, kr, nc));
                bfr[2*njp][0] = r0; bfr[2*njp][1] = r1;
                bfr[2*njp+1][0] = r2; bfr[2*njp+1][1] = r3;
            }
            #pragma unroll
            for (int mi = 0; mi < 4; mi++)
                #pragma unroll
                for (int nj = 0; nj < 4; nj++)
                    mma_bf16(acc[mi][nj], af[mi], bfr[nj]);
        }
    }

    const int g = lane >> 2, tig = lane & 3;
    #pragma unroll
    for (int mi = 0; mi < 4; mi++) {
        #pragma unroll
        for (int r2 = 0; r2 < 2; r2++) {
            int row = bm0 + wm + mi * 16 + g + r2 * 8;
            #pragma unroll
            for (int nj = 0; nj < 4; nj++) {
                int col = bn0 + wn + nj * 8 + tig * 2;
                float v0 = acc[mi][nj][r2 * 2 + 0] + bias[col];
                float v1 = acc[mi][nj][r2 * 2 + 1] + bias[col + 1];
                if (EPI == 1) {
                    float2 rv = *(const float2*)(res + (size_t)row * N + col);
                    v0 += rv.x; v1 += rv.y;
                }
                if (EPI == 3) {
                    v0 = 0.5f * v0 * (1.0f + erff(v0 * 0.7071067811865475f));
                    v1 = 0.5f * v1 * (1.0f + erff(v1 * 0.7071067811865475f));
                    bf16 h0, l0, h1, l1;
                    split_bf16(v0, h0, l0);
                    split_bf16(v1, h1, l1);
                    size_t o = (size_t)row * 3 * N + 3 * col;
                    Ct[o]   = h0; Ct[o+1] = h0; Ct[o+2] = l0;
                    Ct[o+3] = h1; Ct[o+4] = h1; Ct[o+5] = l1;
                } else {
                    *(float2*)(Cf + (size_t)row * N + col) = make_float2(v0, v1);
                }
            }
        }
    }
}

// ---------------------------------------------------------------------------
// Tensor-core flash attention.
// BQ = 64 (4 warps x m16), BKV = 64, D = 64.
// S = Qh*Kh + Qh*Kl + Ql*Kh   (f16 hi/lo split, fp32 accum, Q pre-scaled)
// P = ex2.approx.f16x2((S - m) * log2e)
// O = P*Vh + P*Vl ; l comes from a ones-column at d=64 in Vh.
// K^T tiles [d][pos], V tiles [pos][d+ones], all padded to 72 cols.
// 2-stage cp.async pipeline over KV tiles.
// ---------------------------------------------------------------------------
#define FD 72
#define FTILE (64 * FD)                         // halfs per tile
#define FMHA_SMEM ((2 * FTILE + 2 * 4 * FTILE) * 2)  // Q(hi,lo) + 2 stages x 4 tiles

template<bool CAUSAL>
__global__ void __launch_bounds__(128) fmha_kernel(
    const __half* __restrict__ Qh, const __half* __restrict__ Ql,
    const __half* __restrict__ KTh, const __half* __restrict__ KTl,
    const __half* __restrict__ Vh, const __half* __restrict__ Vl,
    bf16* __restrict__ Op)
{
    const int qt = CAUSAL ? (gridDim.x - 1 - (int)blockIdx.x) : blockIdx.x;
    const int h = blockIdx.y, b = blockIdx.z;
    const int bh = b * H_HEADS + h;
    const int tid = threadIdx.x;
    const int lane = tid & 31, wid = tid >> 5;

    extern __shared__ __half sm[];
    __half* sQh = sm;                 // [64][72]
    __half* sQl = sm + FTILE;
    // stage s: K hi, K lo, V hi, V lo
    auto sK = [&](int s, int hl) { return sm + 2 * FTILE + (s * 4 + hl) * FTILE; };
    auto sV = [&](int s, int hl) { return sm + 2 * FTILE + (s * 4 + 2 + hl) * FTILE; };

    const size_t qbase  = ((size_t)bh * T_SEQ + qt * 64) * 64;
    const size_t ktbase = (size_t)bh * 64 * T_SEQ;       // [d][t]
    const size_t vbase  = (size_t)bh * T_SEQ * 64;       // [t][d]

    const int ntiles = CAUSAL ? (qt + 1) : (T_SEQ / 64);

    // ---- V padding init: col 64 = 1.0 in Vh, cols 64..71 = 0 elsewhere ----
    for (int idx = tid; idx < 64 * 8; idx += 128) {
        int pos = idx >> 3, c = 64 + (idx & 7);
        #pragma unroll
        for (int s = 0; s < 2; s++) {
            sV(s, 0)[pos * FD + c] = (c == 64) ? __float2half(1.0f) : __float2half(0.0f);
            sV(s, 1)[pos * FD + c] = __float2half(0.0f);
        }
    }

    // ---- async loaders ----
    auto load_q = [&]() {
        #pragma unroll
        for (int i = 0; i < 4; i++) {
            int chunk = tid + i * 128;           // 512 chunks
            int r = chunk >> 3, c8 = (chunk & 7) * 8;
            cp16((uint32_t)__cvta_generic_to_shared(sQh + r * FD + c8), Qh + qbase + r * 64 + c8);
            cp16((uint32_t)__cvta_generic_to_shared(sQl + r * FD + c8), Ql + qbase + r * 64 + c8);
        }
    };
    auto load_kv = [&](int s, int kt) {
        #pragma unroll
        for (int i = 0; i < 4; i++) {
            int chunk = tid + i * 128;
            int r = chunk >> 3, c8 = (chunk & 7) * 8;
            // K^T: rows = d, cols = pos
            cp16((uint32_t)__cvta_generic_to_shared(sK(s,0) + r * FD + c8),
                 KTh + ktbase + (size_t)r * T_SEQ + kt * 64 + c8);
            cp16((uint32_t)__cvta_generic_to_shared(sK(s,1) + r * FD + c8),
                 KTl + ktbase + (size_t)r * T_SEQ + kt * 64 + c8);
            // V: rows = pos, cols = d
            cp16((uint32_t)__cvta_generic_to_shared(sV(s,0) + r * FD + c8),
                 Vh + vbase + (size_t)(kt * 64 + r) * 64 + c8);
            cp16((uint32_t)__cvta_generic_to_shared(sV(s,1) + r * FD + c8),
                 Vl + vbase + (size_t)(kt * 64 + r) * 64 + c8);
        }
    };

    load_q();
    load_kv(0, 0);
    asm volatile("cp.async.commit_group;\n" ::);
    if (ntiles > 1) load_kv(1, 1);
    asm volatile("cp.async.commit_group;\n" ::);

    // ---- state ----
    float oa[9][4];
    #pragma unroll
    for (int n = 0; n < 9; n++)
        #pragma unroll
        for (int r = 0; r < 4; r++) oa[n][r] = 0.f;
    float m0 = -1e30f, m1 = -1e30f;

    const int g = lane >> 2, tq = lane & 3;

    for (int kt = 0; kt < ntiles; kt++) {
        const int s = kt & 1;
        asm volatile("cp.async.wait_group 1;\n" ::);
        __syncthreads();

        // ---- S = Q K^T (3 split passes) ----
        float sa[8][4];
        #pragma unroll
        for (int n = 0; n < 8; n++)
            #pragma unroll
            for (int r = 0; r < 4; r++) sa[n][r] = 0.f;

        const __half* Qp[3] = { sQh, sQh, sQl };
        const __half* Kp[3] = { sK(s,0), sK(s,1), sK(s,0) };
        #pragma unroll
        for (int p = 0; p < 3; p++) {
            #pragma unroll
            for (int kc = 0; kc < 4; kc++) {
                uint32_t a[4];
                ldm_x4(a[0], a[1], a[2], a[3],
                    (uint32_t)__cvta_generic_to_shared(
                        Qp[p] + (wid * 16 + (lane & 15)) * FD + kc * 16 + ((lane >> 4) << 3)));
                #pragma unroll
                for (int njp = 0; njp < 4; njp++) {
                    uint32_t r0, r1, r2, r3;
                    ldm_x4_t(r0, r1, r2, r3,
                        (uint32_t)__cvta_generic_to_shared(
                            Kp[p] + (kc * 16 + ((lane >> 3) & 1) * 8 + (lane & 7)) * FD
                                  + njp * 16 + ((lane >> 4) & 1) * 8));
                    uint32_t b0[2] = { r0, r1 }, b1[2] = { r2, r3 };
                    mma_f16(sa[2*njp],   a, b0);
                    mma_f16(sa[2*njp+1], a, b1);
                }
            }
        }

        // ---- causal mask (diagonal tile only) ----
        if (CAUSAL && kt == qt) {
            int q0l = wid * 16 + g;     // local row for c0/c1
            #pragma unroll
            for (int nj = 0; nj < 8; nj++) {
                int c0 = nj * 8 + 2 * tq;
                if (c0     > q0l)     sa[nj][0] = -1e30f;
                if (c0 + 1 > q0l)     sa[nj][1] = -1e30f;
                if (c0     > q0l + 8) sa[nj][2] = -1e30f;
                if (c0 + 1 > q0l + 8) sa[nj][3] = -1e30f;
            }
        }

        // ---- online softmax ----
        float mx0 = -1e30f, mx1 = -1e30f;
        #pragma unroll
        for (int nj = 0; nj < 8; nj++) {
            mx0 = fmaxf(mx0, fmaxf(sa[nj][0], sa[nj][1]));
            mx1 = fmaxf(mx1, fmaxf(sa[nj][2], sa[nj][3]));
        }
        #pragma unroll
        for (int o = 1; o <= 2; o <<= 1) {
            mx0 = fmaxf(mx0, __shfl_xor_sync(0xffffffffu, mx0, o));
            mx1 = fmaxf(mx1, __shfl_xor_sync(0xffffffffu, mx1, o));
        }
        float mn0 = fmaxf(m0, mx0), mn1 = fmaxf(m1, mx1);
        float tm0 = mn0 * L2E, tm1 = mn1 * L2E;
        float corr0 = exp2f(m0 * L2E - tm0);
        float corr1 = exp2f(m1 * L2E - tm1);
        m0 = mn0; m1 = mn1;
        #pragma unroll
        for (int n = 0; n < 9; n++) {
            oa[n][0] *= corr0; oa[n][1] *= corr0;
            oa[n][2] *= corr1; oa[n][3] *= corr1;
        }
        uint32_t pf[8][2];
        #pragma unroll
        for (int nj = 0; nj < 8; nj++) {
            pf[nj][0] = ex2_f16x2(fmaf(sa[nj][0], L2E, -tm0), fmaf(sa[nj][1], L2E, -tm0));
            pf[nj][1] = ex2_f16x2(fmaf(sa[nj][2], L2E, -tm1), fmaf(sa[nj][3], L2E, -tm1));
        }

        // ---- O += P V (2 split passes), ones-column accumulates l ----
        #pragma unroll
        for (int p = 0; p < 2; p++) {
            const __half* Vt = sV(s, p);
            #pragma unroll
            for (int kc = 0; kc < 4; kc++) {
                uint32_t a[4] = { pf[2*kc][0], pf[2*kc][1], pf[2*kc+1][0], pf[2*kc+1][1] };
                #pragma unroll
                for (int njp = 0; njp < 4; njp++) {
                    uint32_t r0, r1, r2, r3;
                    ldm_x4_t(r0, r1, r2, r3,
                        (uint32_t)__cvta_generic_to_shared(
                            Vt + (kc * 16 + ((lane >> 3) & 1) * 8 + (lane & 7)) * FD
                               + njp * 16 + ((lane >> 4) & 1) * 8));
                    uint32_t b0[2] = { r0, r1 }, b1[2] = { r2, r3 };
                    mma_f16(oa[2*njp],   a, b0);
                    mma_f16(oa[2*njp+1], a, b1);
                }
                uint32_t r0, r1;
                ldm_x2_t(r0, r1,
                    (uint32_t)__cvta_generic_to_shared(
                        Vt + (kc * 16 + (lane & 15)) * FD + 64));
                uint32_t b2[2] = { r0, r1 };
                mma_f16(oa[8], a, b2);
            }
        }

        __syncthreads();   // everyone done reading stage s before refill
        if (kt + 2 < ntiles) load_kv(s, kt + 2);
        asm volatile("cp.async.commit_group;\n" ::);
    }

    // ---- finalize: normalize by l (ones-column, lanes tq==0 hold it) ----
    float l0 = __shfl_sync(0xffffffffu, oa[8][0], lane & ~3);
    float l1 = __shfl_sync(0xffffffffu, oa[8][2], lane & ~3);
    float inv0 = 1.0f / l0, inv1 = 1.0f / l1;

    size_t r0 = (size_t)b * T_SEQ + qt * 64 + wid * 16 + g;
    size_t r1 = r0 + 8;
    #pragma unroll
    for (int nj = 0; nj < 8; nj++) {
        int col = h * 64 + nj * 8 + 2 * tq;
        bf16 hi, lo;
        bf16* o0 = Op + r0 * (3 * C_DIM) + 3 * col;
        split_bf16(oa[nj][0] * inv0, hi, lo); o0[0] = hi; o0[1] = hi; o0[2] = lo;
        split_bf16(oa[nj][1] * inv0, hi, lo); o0[3] = hi; o0[4] = hi; o0[5] = lo;
        bf16* o1 = Op + r1 * (3 * C_DIM) + 3 * col;
        split_bf16(oa[nj][2] * inv1, hi, lo); o1[0] = hi; o1[1] = hi; o1[2] = lo;
        split_bf16(oa[nj][3] * inv1, hi, lo); o1[3] = hi; o1[4] = hi; o1[5] = lo;
    }
}

// ---------------------------------------------------------------------------
// Launch
// ---------------------------------------------------------------------------
static inline int cdiv(int a, int b) { return (a + b - 1) / b; }

extern "C" void kernel_launch(void* const* d_in, const int* in_sizes, int n_in,
                              void* d_out, int out_size)
{
    const float* x           = (const float*)d_in[0];
    const float* context     = (const float*)d_in[1];
    const float* ln1_g       = (const float*)d_in[2];
    const float* ln1_b       = (const float*)d_in[3];
    const float* qkv_w       = (const float*)d_in[4];
    const float* qkv_b       = (const float*)d_in[5];
    const float* attn_out_w  = (const float*)d_in[6];
    const float* attn_out_b  = (const float*)d_in[7];
    const float* lnc_g       = (const float*)d_in[8];
    const float* lnc_b       = (const float*)d_in[9];
    const float* q_w         = (const float*)d_in[10];
    const float* q_b         = (const float*)d_in[11];
    const float* kv_w        = (const float*)d_in[12];
    const float* kv_b        = (const float*)d_in[13];
    const float* cross_out_w = (const float*)d_in[14];
    const float* cross_out_b = (const float*)d_in[15];
    const float* ln2_g       = (const float*)d_in[16];
    const float* ln2_b       = (const float*)d_in[17];
    const float* ffn_w1      = (const float*)d_in[18];
    const float* ffn_b1      = (const float*)d_in[19];
    const float* ffn_w2      = (const float*)d_in[20];
    const float* ffn_b2      = (const float*)d_in[21];
    float* out = (float*)d_out;

    float *qkv, *x1, *x2, *q2f, *kvf;
    bf16 *h2, *attn2, *ctx2, *ffn2a;
    bf16 *wqkv2, *wao2, *wq2, *wkv2, *wco2, *wf1, *wf2;
    __half *qh, *ql, *kth, *ktl, *vh, *vl;
    cudaGetSymbolAddress((void**)&qkv,   g_qkv);
    cudaGetSymbolAddress((void**)&x1,    g_x1);
    cudaGetSymbolAddress((void**)&x2,    g_x2);
    cudaGetSymbolAddress((void**)&q2f,   g_q2f);
    cudaGetSymbolAddress((void**)&kvf,   g_kvf);
    cudaGetSymbolAddress((void**)&h2,    g_h2);
    cudaGetSymbolAddress((void**)&attn2, g_attn2);
    cudaGetSymbolAddress((void**)&ctx2,  g_ctx2);
    cudaGetSymbolAddress((void**)&ffn2a, g_ffn2a);
    cudaGetSymbolAddress((void**)&wqkv2, w_qkv2);
    cudaGetSymbolAddress((void**)&wao2,  w_ao2);
    cudaGetSymbolAddress((void**)&wq2,   w_q2);
    cudaGetSymbolAddress((void**)&wkv2,  w_kv2);
    cudaGetSymbolAddress((void**)&wco2,  w_co2);
    cudaGetSymbolAddress((void**)&wf1,   w_f1_2);
    cudaGetSymbolAddress((void**)&wf2,   w_f2_2);
    cudaGetSymbolAddress((void**)&qh,  a_qh);
    cudaGetSymbolAddress((void**)&ql,  a_ql);
    cudaGetSymbolAddress((void**)&kth, a_kth);
    cudaGetSymbolAddress((void**)&ktl, a_ktl);
    cudaGetSymbolAddress((void**)&vh,  a_vh);
    cudaGetSymbolAddress((void**)&vl,  a_vl);

    cudaFuncSetAttribute(bgemm_kernel<0>, cudaFuncAttributeMaxDynamicSharedMemorySize, BG_SMEM);
    cudaFuncSetAttribute(bgemm_kernel<1>, cudaFuncAttributeMaxDynamicSharedMemorySize, BG_SMEM);
    cudaFuncSetAttribute(bgemm_kernel<3>, cudaFuncAttributeMaxDynamicSharedMemorySize, BG_SMEM);
    cudaFuncSetAttribute(fmha_kernel<true>,  cudaFuncAttributeMaxDynamicSharedMemorySize, FMHA_SMEM);
    cudaFuncSetAttribute(fmha_kernel<false>, cudaFuncAttributeMaxDynamicSharedMemorySize, FMHA_SMEM);

    const int M = M_ROWS, C = C_DIM, F = F_DIM;
    dim3 fgrid(T_SEQ / 64, H_HEADS, 4);
    const int PREP_GRID = cdiv(ATT_ELEMS, 256);

    convB_kernel<<<cdiv(C * 3 * C, 256), 256>>>(qkv_w,       wqkv2, C, 3 * C);
    convB_kernel<<<cdiv(C * C,     256), 256>>>(attn_out_w,  wao2,  C, C);
    convB_kernel<<<cdiv(C * C,     256), 256>>>(q_w,         wq2,   C, C);
    convB_kernel<<<cdiv(C * 2 * C, 256), 256>>>(kv_w,        wkv2,  C, 2 * C);
    convB_kernel<<<cdiv(C * C,     256), 256>>>(cross_out_w, wco2,  C, C);
    convB_kernel<<<cdiv(C * F,     256), 256>>>(ffn_w1,      wf1,   C, F);
    convB_kernel<<<cdiv(F * C,     256), 256>>>(ffn_w2,      wf2,   F, C);
    convA_kernel<<<cdiv(M * C,     256), 256>>>(context,     ctx2,  C, M * C);

    // 1) h2 = LN1(x)
    ln_kernel<<<M, 256>>>(x, ln1_g, ln1_b, h2);
    // 2) qkv = h @ qkv_w + qkv_b
    bgemm_kernel<0><<<dim3(3 * C / BN, M / BM), 256, BG_SMEM>>>(
        h2, wqkv2, qkv_b, nullptr, qkv, nullptr, M, 3 * C, 3 * C);
    // 3) pre-split self-attention operands
    prep_rm<<<PREP_GRID, 256>>>(qkv, 3 * C, 0,     0.125f, qh, ql);
    prep_tr<<<PREP_GRID, 256>>>(qkv, 3 * C, C,             kth, ktl);
    prep_rm<<<PREP_GRID, 256>>>(qkv, 3 * C, 2 * C, 1.0f,   vh, vl);
    // 4) self-attention (causal) -> attn2
    fmha_kernel<true><<<fgrid, 128, FMHA_SMEM>>>(qh, ql, kth, ktl, vh, vl, attn2);
    // 5) x1 = x + attn @ attn_out_w + attn_out_b
    bgemm_kernel<1><<<dim3(C / BN, M / BM), 256, BG_SMEM>>>(
        attn2, wao2, attn_out_b, x, x1, nullptr, M, C, 3 * C);
    // 6) h2 = LNc(x1)
    ln_kernel<<<M, 256>>>(x1, lnc_g, lnc_b, h2);
    // 7) q2 = h @ q_w + q_b ; kv = context @ kv_w + kv_b
    bgemm_kernel<0><<<dim3(C / BN, M / BM), 256, BG_SMEM>>>(
        h2, wq2, q_b, nullptr, q2f, nullptr, M, C, 3 * C);
    bgemm_kernel<0><<<dim3(2 * C / BN, M / BM), 256, BG_SMEM>>>(
        ctx2, wkv2, kv_b, nullptr, kvf, nullptr, M, 2 * C, 3 * C);
    // 8) pre-split cross-attention operands
    prep_rm<<<PREP_GRID, 256>>>(q2f, C,     0, 0.125f, qh, ql);
    prep_tr<<<PREP_GRID, 256>>>(kvf, 2 * C, 0,         kth, ktl);
    prep_rm<<<PREP_GRID, 256>>>(kvf, 2 * C, C, 1.0f,   vh, vl);
    // 9) cross-attention -> attn2
    fmha_kernel<false><<<fgrid, 128, FMHA_SMEM>>>(qh, ql, kth, ktl, vh, vl, attn2);
    // 10) x2 = x1 + attn @ cross_out_w + cross_out_b
    bgemm_kernel<1><<<dim3(C / BN, M / BM), 256, BG_SMEM>>>(
        attn2, wco2, cross_out_b, x1, x2, nullptr, M, C, 3 * C);
    // 11) h2 = LN2(x2)
    ln_kernel<<<M, 256>>>(x2, ln2_g, ln2_b, h2);
    // 12) ffn2a = triple(gelu(h @ ffn_w1 + ffn_b1))
    bgemm_kernel<3><<<dim3(F / BN, M / BM), 256, BG_SMEM>>>(
        h2, wf1, ffn_b1, nullptr, nullptr, ffn2a, M, F, 3 * C);
    // 13) out = x2 + ffn @ ffn_w2 + ffn_b2
    bgemm_kernel<1><<<dim3(C / BN, M / BM), 256, BG_SMEM>>>(
        ffn2a, wf2, ffn_b2, x2, out, nullptr, M, C, 3 * F);
}

// round 5
// speedup vs baseline: 2.3423x; 1.1176x over previous
#include <cuda_runtime.h>
#include <cuda_bf16.h>
#include <cuda_fp16.h>
#include <cstdint>
#include <math.h>

typedef __nv_bfloat16 bf16;

// ---------------------------------------------------------------------------
// Problem constants: B=4, T=1024, C=1024, H=16, D=64, F=4096, M=B*T=4096
// ---------------------------------------------------------------------------
#define M_ROWS 4096
#define C_DIM  1024
#define T_SEQ  1024
#define H_HEADS 16
#define F_DIM  4096
#define L2E 1.4426950408889634f

// ---------------------------------------------------------------------------
// Scratch (device globals)
// ---------------------------------------------------------------------------
__device__ float g_qkv[M_ROWS * 3 * C_DIM];
__device__ float g_x1 [M_ROWS * C_DIM];
__device__ float g_x2 [M_ROWS * C_DIM];
__device__ float g_q2f[M_ROWS * C_DIM];
__device__ float g_kvf[M_ROWS * 2 * C_DIM];

__device__ bf16 g_h2   [M_ROWS * 3 * C_DIM];          // LN out (triple hi,hi,lo)
__device__ bf16 g_attn2[M_ROWS * 3 * C_DIM];
__device__ bf16 g_ctx2 [M_ROWS * 3 * C_DIM];
__device__ bf16 g_ffn2a[(size_t)M_ROWS * 3 * F_DIM];

// Weights: [3K][N] bf16 rows (hi, lo, hi) — B operand of mma.sync GEMM
__device__ bf16 w_qkv2[3 * C_DIM * 3 * C_DIM];
__device__ bf16 w_ao2 [3 * C_DIM * C_DIM];
__device__ bf16 w_q2  [3 * C_DIM * C_DIM];
__device__ bf16 w_kv2 [3 * C_DIM * 2 * C_DIM];
__device__ bf16 w_co2 [3 * C_DIM * C_DIM];
__device__ bf16 w_f1_2[3 * C_DIM * F_DIM];
__device__ bf16 w_f2_2[(size_t)3 * F_DIM * C_DIM];

#define ATT_ELEMS (4 * H_HEADS * T_SEQ * 64)
__device__ __half a_qh[ATT_ELEMS];
__device__ __half a_ql[ATT_ELEMS];
__device__ __half a_kth[ATT_ELEMS];
__device__ __half a_ktl[ATT_ELEMS];
__device__ __half a_vh[ATT_ELEMS];
__device__ __half a_vl[ATT_ELEMS];

// ---------------------------------------------------------------------------
// Helpers
// ---------------------------------------------------------------------------
__device__ __forceinline__ void split_bf16(float x, bf16& hi, bf16& lo) {
    hi = __float2bfloat16(x);
    lo = __float2bfloat16(x - __bfloat162float(hi));
}

__device__ __forceinline__ void cp16(uint32_t dst, const void* src) {
    asm volatile("cp.async.cg.shared.global [%0], [%1], 16;\n" :: "r"(dst), "l"(src));
}
__device__ __forceinline__ void ldm_x4(uint32_t& r0, uint32_t& r1, uint32_t& r2,
                                       uint32_t& r3, uint32_t addr) {
    asm volatile("ldmatrix.sync.aligned.m8n8.x4.shared.b16 {%0,%1,%2,%3}, [%4];\n"
        : "=r"(r0), "=r"(r1), "=r"(r2), "=r"(r3) : "r"(addr));
}
__device__ __forceinline__ void ldm_x4_t(uint32_t& r0, uint32_t& r1, uint32_t& r2,
                                         uint32_t& r3, uint32_t addr) {
    asm volatile("ldmatrix.sync.aligned.m8n8.x4.trans.shared.b16 {%0,%1,%2,%3}, [%4];\n"
        : "=r"(r0), "=r"(r1), "=r"(r2), "=r"(r3) : "r"(addr));
}
__device__ __forceinline__ void ldm_x2_t(uint32_t& r0, uint32_t& r1, uint32_t addr) {
    asm volatile("ldmatrix.sync.aligned.m8n8.x2.trans.shared.b16 {%0,%1}, [%2];\n"
        : "=r"(r0), "=r"(r1) : "r"(addr));
}
__device__ __forceinline__ void mma_bf16(float* d, const uint32_t* a, const uint32_t* b) {
    asm volatile("mma.sync.aligned.m16n8k16.row.col.f32.bf16.bf16.f32 "
        "{%0,%1,%2,%3}, {%4,%5,%6,%7}, {%8,%9}, {%0,%1,%2,%3};\n"
        : "+f"(d[0]), "+f"(d[1]), "+f"(d[2]), "+f"(d[3])
        : "r"(a[0]), "r"(a[1]), "r"(a[2]), "r"(a[3]), "r"(b[0]), "r"(b[1]));
}
__device__ __forceinline__ void mma_f16(float* d, const uint32_t* a, const uint32_t* b) {
    asm volatile("mma.sync.aligned.m16n8k16.row.col.f32.f16.f16.f32 "
        "{%0,%1,%2,%3}, {%4,%5,%6,%7}, {%8,%9}, {%0,%1,%2,%3};\n"
        : "+f"(d[0]), "+f"(d[1]), "+f"(d[2]), "+f"(d[3])
        : "r"(a[0]), "r"(a[1]), "r"(a[2]), "r"(a[3]), "r"(b[0]), "r"(b[1]));
}
__device__ __forceinline__ uint32_t ex2_f16x2(float a, float b) {
    __half2 h = __floats2half2_rn(a, b);
    uint32_t u = *reinterpret_cast<uint32_t*>(&h);
    uint32_t r;
    asm volatile("ex2.approx.f16x2 %0, %1;\n" : "=r"(r) : "r"(u));
    return r;
}

// ---------------------------------------------------------------------------
// Weight conversion: src [K][N] fp32 -> dst [3K][N] bf16 rows (hi, lo, hi)
// ---------------------------------------------------------------------------
__global__ void convB_kernel(const float* __restrict__ src, bf16* __restrict__ dst,
                             int K, int N) {
    int e = blockIdx.x * 256 + threadIdx.x;
    if (e >= K * N) return;
    int k = e / N, n = e % N;
    bf16 hi, lo; split_bf16(src[e], hi, lo);
    size_t o = (size_t)(3 * k) * N + n;
    dst[o] = hi; dst[o + N] = lo; dst[o + 2 * N] = hi;
}

// Activation conversion: src [M][K] fp32 -> dst [M][3K] bf16 (hi,hi,lo)
__global__ void convA_kernel(const float* __restrict__ src, bf16* __restrict__ dst,
                             int K, int total) {
    int e = blockIdx.x * 256 + threadIdx.x;
    if (e >= total) return;
    int m = e / K, k = e % K;
    bf16 hi, lo; split_bf16(src[e], hi, lo);
    size_t o = (size_t)m * 3 * K + 3 * k;
    dst[o] = hi; dst[o + 1] = hi; dst[o + 2] = lo;
}

// ---------------------------------------------------------------------------
// Attention pre-split kernels
// ---------------------------------------------------------------------------
__global__ void prep_rm(const float* __restrict__ in, int rowstride, int coloff,
                        float scale, __half* __restrict__ oh, __half* __restrict__ ol) {
    int idx = blockIdx.x * 256 + threadIdx.x;
    if (idx >= ATT_ELEMS) return;
    int d = idx & 63;
    int t = (idx >> 6) & 1023;
    int h = (idx >> 16) & 15;
    int b = idx >> 20;
    float v = in[(size_t)(b * 1024 + t) * rowstride + coloff + h * 64 + d] * scale;
    __half hi = __float2half_rn(v);
    __half lo = __float2half_rn(v - __half2float(hi));
    size_t o = ((size_t)((b * 16 + h) * 1024) + t) * 64 + d;
    oh[o] = hi; ol[o] = lo;
}

__global__ void prep_tr(const float* __restrict__ in, int rowstride, int coloff,
                        __half* __restrict__ oh, __half* __restrict__ ol) {
    int idx = blockIdx.x * 256 + threadIdx.x;
    if (idx >= ATT_ELEMS) return;
    int t = idx & 1023;
    int d = (idx >> 10) & 63;
    int h = (idx >> 16) & 15;
    int b = idx >> 20;
    float v = in[(size_t)(b * 1024 + t) * rowstride + coloff + h * 64 + d];
    __half hi = __float2half_rn(v);
    __half lo = __float2half_rn(v - __half2float(hi));
    size_t o = ((size_t)((b * 16 + h) * 64 + d)) * 1024 + t;
    oh[o] = hi; ol[o] = lo;
}

// ---------------------------------------------------------------------------
// LayerNorm (writes bf16 triple)
// ---------------------------------------------------------------------------
__global__ void __launch_bounds__(256) ln_kernel(
    const float* __restrict__ x, const float* __restrict__ g,
    const float* __restrict__ b, bf16* __restrict__ out)
{
    int row = blockIdx.x;
    int tid = threadIdx.x;
    float4 v = ((const float4*)(x + (size_t)row * C_DIM))[tid];
    float s  = v.x + v.y + v.z + v.w;
    float s2 = v.x*v.x + v.y*v.y + v.z*v.z + v.w*v.w;
    __shared__ float red[64];
    #pragma unroll
    for (int o = 16; o; o >>= 1) {
        s  += __shfl_xor_sync(0xffffffffu, s,  o);
        s2 += __shfl_xor_sync(0xffffffffu, s2, o);
    }
    int warp = tid >> 5;
    if ((tid & 31) == 0) { red[warp] = s; red[32 + warp] = s2; }
    __syncthreads();
    if (tid < 32) {
        s  = (tid < 8) ? red[tid]      : 0.f;
        s2 = (tid < 8) ? red[32 + tid] : 0.f;
        #pragma unroll
        for (int o = 4; o; o >>= 1) {
            s  += __shfl_xor_sync(0xffffffffu, s,  o);
            s2 += __shfl_xor_sync(0xffffffffu, s2, o);
        }
        if (tid == 0) { red[0] = s; red[32] = s2; }
    }
    __syncthreads();
    float mean = red[0]  * (1.0f / C_DIM);
    float var  = red[32] * (1.0f / C_DIM) - mean * mean;
    float inv  = rsqrtf(var + 1e-5f);
    float4 gv = ((const float4*)g)[tid];
    float4 bv = ((const float4*)b)[tid];
    float ov[4];
    ov[0] = (v.x - mean) * inv * gv.x + bv.x;
    ov[1] = (v.y - mean) * inv * gv.y + bv.y;
    ov[2] = (v.z - mean) * inv * gv.z + bv.z;
    ov[3] = (v.w - mean) * inv * gv.w + bv.w;
    bf16* o = out + (size_t)row * 3 * C_DIM + 12 * tid;
    #pragma unroll
    for (int j = 0; j < 4; j++) {
        bf16 hi, lo; split_bf16(ov[j], hi, lo);
        o[3*j] = hi; o[3*j+1] = hi; o[3*j+2] = lo;
    }
}

// ---------------------------------------------------------------------------
// bf16 tensor-core GEMM v2:  C[M,N] = A[M,Kp] @ B[Kp,N] + bias ...
// BM=BN=128, BK=32, 128 threads (4 warps, 2x2), warp tile 64x64,
// 4-stage cp.async pipeline, exact tail wait. 2 CTAs/SM.
// EPI: 0 = +bias, 1 = +bias+res, 3 = +bias, exact GELU, bf16 triple out.
// ---------------------------------------------------------------------------
#define BM 128
#define BN 128
#define BK 32
#define A_PAD 40    // bf16 elems per A smem row (80 B)
#define B_PAD 136   // bf16 elems per B smem row (272 B)
#define NSTAGE 4
#define BG_SMEM (NSTAGE * (BM * A_PAD + BK * B_PAD) * 2)   // 75776 B

template<int EPI>
__global__ void __launch_bounds__(128, 2) bgemm_kernel(
    const bf16* __restrict__ A, const bf16* __restrict__ Bm,
    const float* __restrict__ bias, const float* __restrict__ res,
    float* __restrict__ Cf, bf16* __restrict__ Ct, int M, int N, int Kp)
{
    extern __shared__ char sm_raw[];
    bf16* As = (bf16*)sm_raw;                                        // [4][128][40]
    bf16* Bs = (bf16*)(sm_raw + NSTAGE * BM * A_PAD * sizeof(bf16)); // [4][32][136]

    const int tid  = threadIdx.x;
    const int lane = tid & 31, wid = tid >> 5;
    const int bm0 = blockIdx.y * BM, bn0 = blockIdx.x * BN;
    const int wm = (wid & 1) * 64, wn = (wid >> 1) * 64;

    float acc[4][8][4];
    #pragma unroll
    for (int i = 0; i < 4; i++)
        #pragma unroll
        for (int j = 0; j < 8; j++)
            #pragma unroll
            for (int r = 0; r < 4; r++) acc[i][j][r] = 0.f;

    auto As_u32 = [&](int s, int r, int c) -> uint32_t {
        return (uint32_t)__cvta_generic_to_shared(As + ((s * BM + r) * A_PAD + c));
    };
    auto Bs_u32 = [&](int s, int r, int c) -> uint32_t {
        return (uint32_t)__cvta_generic_to_shared(Bs + ((s * BK + r) * B_PAD + c));
    };

    // A: 128x32 = 512 chunks of 8; B: 32x128 = 512 chunks. 128 threads -> 4 each.
    auto load_stage = [&](int s, int k0) {
        #pragma unroll
        for (int i = 0; i < 4; i++) {
            int chunk = tid + i * 128;
            int ar = chunk >> 2, ac = (chunk & 3) * 8;
            cp16(As_u32(s, ar, ac), A + (size_t)(bm0 + ar) * Kp + k0 + ac);
            int br = chunk >> 4, bc = (chunk & 15) * 8;
            cp16(Bs_u32(s, br, bc), Bm + (size_t)(k0 + br) * N + bn0 + bc);
        }
        asm volatile("cp.async.commit_group;\n" ::);
    };

    const int NK = Kp / BK;
    load_stage(0, 0);
    load_stage(1, BK);
    load_stage(2, 2 * BK);

    for (int t = 0; t < NK; t++) {
        const int rem = NK - 1 - t;
        if (rem >= 2)      asm volatile("cp.async.wait_group 2;\n" ::);
        else if (rem == 1) asm volatile("cp.async.wait_group 1;\n" ::);
        else               asm volatile("cp.async.wait_group 0;\n" ::);
        __syncthreads();
        if (t + 3 < NK) load_stage((t + 3) & 3, (t + 3) * BK);
        const int s = t & 3;

        #pragma unroll
        for (int k16 = 0; k16 < 2; k16++) {
            uint32_t af[4][4];
            #pragma unroll
            for (int mi = 0; mi < 4; mi++) {
                uint32_t addr = As_u32(s, wm + mi * 16 + (lane & 15),
                                       k16 * 16 + ((lane >> 4) << 3));
                ldm_x4(af[mi][0], af[mi][1], af[mi][2], af[mi][3], addr);
            }
            uint32_t bfr[8][2];
            #pragma unroll
            for (int njp = 0; njp < 4; njp++) {
                int kr = k16 * 16 + ((lane >> 3) & 1) * 8 + (lane & 7);
                int nc = wn + njp * 16 + ((lane >> 4) & 1) * 8;
                uint32_t r0, r1, r2, r3;
                ldm_x4_t(r0, r1, r2, r3, Bs_u32(s, kr, nc));
                bfr[2*njp][0] = r0; bfr[2*njp][1] = r1;
                bfr[2*njp+1][0] = r2; bfr[2*njp+1][1] = r3;
            }
            #pragma unroll
            for (int mi = 0; mi < 4; mi++)
                #pragma unroll
                for (int nj = 0; nj < 8; nj++)
                    mma_bf16(acc[mi][nj], af[mi], bfr[nj]);
        }
        __syncthreads();
    }

    // Epilogue
    const int g = lane >> 2, tig = lane & 3;
    #pragma unroll
    for (int mi = 0; mi < 4; mi++) {
        #pragma unroll
        for (int r2 = 0; r2 < 2; r2++) {
            int row = bm0 + wm + mi * 16 + g + r2 * 8;
            #pragma unroll
            for (int nj = 0; nj < 8; nj++) {
                int col = bn0 + wn + nj * 8 + tig * 2;
                float v0 = acc[mi][nj][r2 * 2 + 0] + bias[col];
                float v1 = acc[mi][nj][r2 * 2 + 1] + bias[col + 1];
                if (EPI == 1) {
                    float2 rv = *(const float2*)(res + (size_t)row * N + col);
                    v0 += rv.x; v1 += rv.y;
                }
                if (EPI == 3) {
                    v0 = 0.5f * v0 * (1.0f + erff(v0 * 0.7071067811865475f));
                    v1 = 0.5f * v1 * (1.0f + erff(v1 * 0.7071067811865475f));
                    bf16 h0, l0, h1, l1;
                    split_bf16(v0, h0, l0);
                    split_bf16(v1, h1, l1);
                    size_t o = (size_t)row * 3 * N + 3 * col;
                    Ct[o]   = h0; Ct[o+1] = h0; Ct[o+2] = l0;
                    Ct[o+3] = h1; Ct[o+4] = h1; Ct[o+5] = l1;
                } else {
                    *(float2*)(Cf + (size_t)row * N + col) = make_float2(v0, v1);
                }
            }
        }
    }
}

// ---------------------------------------------------------------------------
// Tensor-core flash attention (unchanged from R2, proven at 2122us)
// ---------------------------------------------------------------------------
#define FD 72
#define FTILE (64 * FD)
#define FMHA_SMEM ((2 * FTILE + 2 * 4 * FTILE) * 2)

template<bool CAUSAL>
__global__ void __launch_bounds__(128) fmha_kernel(
    const __half* __restrict__ Qh, const __half* __restrict__ Ql,
    const __half* __restrict__ KTh, const __half* __restrict__ KTl,
    const __half* __restrict__ Vh, const __half* __restrict__ Vl,
    bf16* __restrict__ Op)
{
    const int qt = CAUSAL ? (gridDim.x - 1 - (int)blockIdx.x) : blockIdx.x;
    const int h = blockIdx.y, b = blockIdx.z;
    const int bh = b * H_HEADS + h;
    const int tid = threadIdx.x;
    const int lane = tid & 31, wid = tid >> 5;

    extern __shared__ __half sm[];
    __half* sQh = sm;
    __half* sQl = sm + FTILE;
    auto sK = [&](int s, int hl) { return sm + 2 * FTILE + (s * 4 + hl) * FTILE; };
    auto sV = [&](int s, int hl) { return sm + 2 * FTILE + (s * 4 + 2 + hl) * FTILE; };

    const size_t qbase  = ((size_t)bh * T_SEQ + qt * 64) * 64;
    const size_t ktbase = (size_t)bh * 64 * T_SEQ;
    const size_t vbase  = (size_t)bh * T_SEQ * 64;

    const int ntiles = CAUSAL ? (qt + 1) : (T_SEQ / 64);

    for (int idx = tid; idx < 64 * 8; idx += 128) {
        int pos = idx >> 3, c = 64 + (idx & 7);
        #pragma unroll
        for (int s = 0; s < 2; s++) {
            sV(s, 0)[pos * FD + c] = (c == 64) ? __float2half(1.0f) : __float2half(0.0f);
            sV(s, 1)[pos * FD + c] = __float2half(0.0f);
        }
    }

    auto load_q = [&]() {
        #pragma unroll
        for (int i = 0; i < 4; i++) {
            int chunk = tid + i * 128;
            int r = chunk >> 3, c8 = (chunk & 7) * 8;
            cp16((uint32_t)__cvta_generic_to_shared(sQh + r * FD + c8), Qh + qbase + r * 64 + c8);
            cp16((uint32_t)__cvta_generic_to_shared(sQl + r * FD + c8), Ql + qbase + r * 64 + c8);
        }
    };
    auto load_kv = [&](int s, int kt) {
        #pragma unroll
        for (int i = 0; i < 4; i++) {
            int chunk = tid + i * 128;
            int r = chunk >> 3, c8 = (chunk & 7) * 8;
            cp16((uint32_t)__cvta_generic_to_shared(sK(s,0) + r * FD + c8),
                 KTh + ktbase + (size_t)r * T_SEQ + kt * 64 + c8);
            cp16((uint32_t)__cvta_generic_to_shared(sK(s,1) + r * FD + c8),
                 KTl + ktbase + (size_t)r * T_SEQ + kt * 64 + c8);
            cp16((uint32_t)__cvta_generic_to_shared(sV(s,0) + r * FD + c8),
                 Vh + vbase + (size_t)(kt * 64 + r) * 64 + c8);
            cp16((uint32_t)__cvta_generic_to_shared(sV(s,1) + r * FD + c8),
                 Vl + vbase + (size_t)(kt * 64 + r) * 64 + c8);
        }
    };

    load_q();
    load_kv(0, 0);
    asm volatile("cp.async.commit_group;\n" ::);
    if (ntiles > 1) load_kv(1, 1);
    asm volatile("cp.async.commit_group;\n" ::);

    float oa[9][4];
    #pragma unroll
    for (int n = 0; n < 9; n++)
        #pragma unroll
        for (int r = 0; r < 4; r++) oa[n][r] = 0.f;
    float m0 = -1e30f, m1 = -1e30f;

    const int g = lane >> 2, tq = lane & 3;

    for (int kt = 0; kt < ntiles; kt++) {
        const int s = kt & 1;
        if (kt + 1 < ntiles) asm volatile("cp.async.wait_group 1;\n" ::);
        else                 asm volatile("cp.async.wait_group 0;\n" ::);
        __syncthreads();

        float sa[8][4];
        #pragma unroll
        for (int n = 0; n < 8; n++)
            #pragma unroll
            for (int r = 0; r < 4; r++) sa[n][r] = 0.f;

        const __half* Qp[3] = { sQh, sQh, sQl };
        const __half* Kp[3] = { sK(s,0), sK(s,1), sK(s,0) };
        #pragma unroll
        for (int p = 0; p < 3; p++) {
            #pragma unroll
            for (int kc = 0; kc < 4; kc++) {
                uint32_t a[4];
                ldm_x4(a[0], a[1], a[2], a[3],
                    (uint32_t)__cvta_generic_to_shared(
                        Qp[p] + (wid * 16 + (lane & 15)) * FD + kc * 16 + ((lane >> 4) << 3)));
                #pragma unroll
                for (int njp = 0; njp < 4; njp++) {
                    uint32_t r0, r1, r2, r3;
                    ldm_x4_t(r0, r1, r2, r3,
                        (uint32_t)__cvta_generic_to_shared(
                            Kp[p] + (kc * 16 + ((lane >> 3) & 1) * 8 + (lane & 7)) * FD
                                  + njp * 16 + ((lane >> 4) & 1) * 8));
                    uint32_t b0[2] = { r0, r1 }, b1[2] = { r2, r3 };
                    mma_f16(sa[2*njp],   a, b0);
                    mma_f16(sa[2*njp+1], a, b1);
                }
            }
        }

        if (CAUSAL && kt == qt) {
            int q0l = wid * 16 + g;
            #pragma unroll
            for (int nj = 0; nj < 8; nj++) {
                int c0 = nj * 8 + 2 * tq;
                if (c0     > q0l)     sa[nj][0] = -1e30f;
                if (c0 + 1 > q0l)     sa[nj][1] = -1e30f;
                if (c0     > q0l + 8) sa[nj][2] = -1e30f;
                if (c0 + 1 > q0l + 8) sa[nj][3] = -1e30f;
            }
        }

        float mx0 = -1e30f, mx1 = -1e30f;
        #pragma unroll
        for (int nj = 0; nj < 8; nj++) {
            mx0 = fmaxf(mx0, fmaxf(sa[nj][0], sa[nj][1]));
            mx1 = fmaxf(mx1, fmaxf(sa[nj][2], sa[nj][3]));
        }
        #pragma unroll
        for (int o = 1; o <= 2; o <<= 1) {
            mx0 = fmaxf(mx0, __shfl_xor_sync(0xffffffffu, mx0, o));
            mx1 = fmaxf(mx1, __shfl_xor_sync(0xffffffffu, mx1, o));
        }
        float mn0 = fmaxf(m0, mx0), mn1 = fmaxf(m1, mx1);
        float tm0 = mn0 * L2E, tm1 = mn1 * L2E;
        float corr0 = exp2f(m0 * L2E - tm0);
        float corr1 = exp2f(m1 * L2E - tm1);
        m0 = mn0; m1 = mn1;
        #pragma unroll
        for (int n = 0; n < 9; n++) {
            oa[n][0] *= corr0; oa[n][1] *= corr0;
            oa[n][2] *= corr1; oa[n][3] *= corr1;
        }
        uint32_t pf[8][2];
        #pragma unroll
        for (int nj = 0; nj < 8; nj++) {
            pf[nj][0] = ex2_f16x2(fmaf(sa[nj][0], L2E, -tm0), fmaf(sa[nj][1], L2E, -tm0));
            pf[nj][1] = ex2_f16x2(fmaf(sa[nj][2], L2E, -tm1), fmaf(sa[nj][3], L2E, -tm1));
        }

        #pragma unroll
        for (int p = 0; p < 2; p++) {
            const __half* Vt = sV(s, p);
            #pragma unroll
            for (int kc = 0; kc < 4; kc++) {
                uint32_t a[4] = { pf[2*kc][0], pf[2*kc][1], pf[2*kc+1][0], pf[2*kc+1][1] };
                #pragma unroll
                for (int njp = 0; njp < 4; njp++) {
                    uint32_t r0, r1, r2, r3;
                    ldm_x4_t(r0, r1, r2, r3,
                        (uint32_t)__cvta_generic_to_shared(
                            Vt + (kc * 16 + ((lane >> 3) & 1) * 8 + (lane & 7)) * FD
                               + njp * 16 + ((lane >> 4) & 1) * 8));
                    uint32_t b0[2] = { r0, r1 }, b1[2] = { r2, r3 };
                    mma_f16(oa[2*njp],   a, b0);
                    mma_f16(oa[2*njp+1], a, b1);
                }
                uint32_t r0, r1;
                ldm_x2_t(r0, r1,
                    (uint32_t)__cvta_generic_to_shared(
                        Vt + (kc * 16 + (lane & 15)) * FD + 64));
                uint32_t b2[2] = { r0, r1 };
                mma_f16(oa[8], a, b2);
            }
        }

        __syncthreads();
        if (kt + 2 < ntiles) load_kv(s, kt + 2);
        asm volatile("cp.async.commit_group;\n" ::);
    }

    float l0 = __shfl_sync(0xffffffffu, oa[8][0], lane & ~3);
    float l1 = __shfl_sync(0xffffffffu, oa[8][2], lane & ~3);
    float inv0 = 1.0f / l0, inv1 = 1.0f / l1;

    size_t r0 = (size_t)b * T_SEQ + qt * 64 + wid * 16 + g;
    size_t r1 = r0 + 8;
    #pragma unroll
    for (int nj = 0; nj < 8; nj++) {
        int col = h * 64 + nj * 8 + 2 * tq;
        bf16 hi, lo;
        bf16* o0 = Op + r0 * (3 * C_DIM) + 3 * col;
        split_bf16(oa[nj][0] * inv0, hi, lo); o0[0] = hi; o0[1] = hi; o0[2] = lo;
        split_bf16(oa[nj][1] * inv0, hi, lo); o0[3] = hi; o0[4] = hi; o0[5] = lo;
        bf16* o1 = Op + r1 * (3 * C_DIM) + 3 * col;
        split_bf16(oa[nj][2] * inv1, hi, lo); o1[0] = hi; o1[1] = hi; o1[2] = lo;
        split_bf16(oa[nj][3] * inv1, hi, lo); o1[3] = hi; o1[4] = hi; o1[5] = lo;
    }
}

// ---------------------------------------------------------------------------
// Launch.  NOTE: launch order arranged so the 6th launch (ncu -s 5 -c 1
// profiles exactly that one) is the big qkv GEMM, not a tiny conv kernel.
// ---------------------------------------------------------------------------
static inline int cdiv(int a, int b) { return (a + b - 1) / b; }

extern "C" void kernel_launch(void* const* d_in, const int* in_sizes, int n_in,
                              void* d_out, int out_size)
{
    const float* x           = (const float*)d_in[0];
    const float* context     = (const float*)d_in[1];
    const float* ln1_g       = (const float*)d_in[2];
    const float* ln1_b       = (const float*)d_in[3];
    const float* qkv_w       = (const float*)d_in[4];
    const float* qkv_b       = (const float*)d_in[5];
    const float* attn_out_w  = (const float*)d_in[6];
    const float* attn_out_b  = (const float*)d_in[7];
    const float* lnc_g       = (const float*)d_in[8];
    const float* lnc_b       = (const float*)d_in[9];
    const float* q_w         = (const float*)d_in[10];
    const float* q_b         = (const float*)d_in[11];
    const float* kv_w        = (const float*)d_in[12];
    const float* kv_b        = (const float*)d_in[13];
    const float* cross_out_w = (const float*)d_in[14];
    const float* cross_out_b = (const float*)d_in[15];
    const float* ln2_g       = (const float*)d_in[16];
    const float* ln2_b       = (const float*)d_in[17];
    const float* ffn_w1      = (const float*)d_in[18];
    const float* ffn_b1      = (const float*)d_in[19];
    const float* ffn_w2      = (const float*)d_in[20];
    const float* ffn_b2      = (const float*)d_in[21];
    float* out = (float*)d_out;

    float *qkv, *x1, *x2, *q2f, *kvf;
    bf16 *h2, *attn2, *ctx2, *ffn2a;
    bf16 *wqkv2, *wao2, *wq2, *wkv2, *wco2, *wf1, *wf2;
    __half *qh, *ql, *kth, *ktl, *vh, *vl;
    cudaGetSymbolAddress((void**)&qkv,   g_qkv);
    cudaGetSymbolAddress((void**)&x1,    g_x1);
    cudaGetSymbolAddress((void**)&x2,    g_x2);
    cudaGetSymbolAddress((void**)&q2f,   g_q2f);
    cudaGetSymbolAddress((void**)&kvf,   g_kvf);
    cudaGetSymbolAddress((void**)&h2,    g_h2);
    cudaGetSymbolAddress((void**)&attn2, g_attn2);
    cudaGetSymbolAddress((void**)&ctx2,  g_ctx2);
    cudaGetSymbolAddress((void**)&ffn2a, g_ffn2a);
    cudaGetSymbolAddress((void**)&wqkv2, w_qkv2);
    cudaGetSymbolAddress((void**)&wao2,  w_ao2);
    cudaGetSymbolAddress((void**)&wq2,   w_q2);
    cudaGetSymbolAddress((void**)&wkv2,  w_kv2);
    cudaGetSymbolAddress((void**)&wco2,  w_co2);
    cudaGetSymbolAddress((void**)&wf1,   w_f1_2);
    cudaGetSymbolAddress((void**)&wf2,   w_f2_2);
    cudaGetSymbolAddress((void**)&qh,  a_qh);
    cudaGetSymbolAddress((void**)&ql,  a_ql);
    cudaGetSymbolAddress((void**)&kth, a_kth);
    cudaGetSymbolAddress((void**)&ktl, a_ktl);
    cudaGetSymbolAddress((void**)&vh,  a_vh);
    cudaGetSymbolAddress((void**)&vl,  a_vl);

    cudaFuncSetAttribute(bgemm_kernel<0>, cudaFuncAttributeMaxDynamicSharedMemorySize, BG_SMEM);
    cudaFuncSetAttribute(bgemm_kernel<1>, cudaFuncAttributeMaxDynamicSharedMemorySize, BG_SMEM);
    cudaFuncSetAttribute(bgemm_kernel<3>, cudaFuncAttributeMaxDynamicSharedMemorySize, BG_SMEM);
    cudaFuncSetAttribute(fmha_kernel<true>,  cudaFuncAttributeMaxDynamicSharedMemorySize, FMHA_SMEM);
    cudaFuncSetAttribute(fmha_kernel<false>, cudaFuncAttributeMaxDynamicSharedMemorySize, FMHA_SMEM);

    const int M = M_ROWS, C = C_DIM, F = F_DIM;
    dim3 fgrid(T_SEQ / 64, H_HEADS, 4);
    const int PREP_GRID = cdiv(ATT_ELEMS, 256);

    // --- launches 1-5: deps of qkv GEMM + fillers ---
    convB_kernel<<<cdiv(C * 3 * C, 256), 256>>>(qkv_w,       wqkv2, C, 3 * C);  // 1
    ln_kernel<<<M, 256>>>(x, ln1_g, ln1_b, h2);                                  // 2
    convB_kernel<<<cdiv(C * C,     256), 256>>>(attn_out_w,  wao2,  C, C);       // 3
    convB_kernel<<<cdiv(C * C,     256), 256>>>(q_w,         wq2,   C, C);       // 4
    convB_kernel<<<cdiv(C * 2 * C, 256), 256>>>(kv_w,        wkv2,  C, 2 * C);   // 5
    // --- launch 6 (ncu profiles this one): qkv GEMM ---
    bgemm_kernel<0><<<dim3(3 * C / BN, M / BM), 128, BG_SMEM>>>(
        h2, wqkv2, qkv_b, nullptr, qkv, nullptr, M, 3 * C, 3 * C);               // 6
    // --- remaining conversions ---
    convB_kernel<<<cdiv(C * C,     256), 256>>>(cross_out_w, wco2,  C, C);
    convB_kernel<<<cdiv(C * F,     256), 256>>>(ffn_w1,      wf1,   C, F);
    convB_kernel<<<cdiv(F * C,     256), 256>>>(ffn_w2,      wf2,   F, C);
    convA_kernel<<<cdiv(M * C,     256), 256>>>(context,     ctx2,  C, M * C);

    // self-attention
    prep_rm<<<PREP_GRID, 256>>>(qkv, 3 * C, 0,     0.125f, qh, ql);
    prep_tr<<<PREP_GRID, 256>>>(qkv, 3 * C, C,             kth, ktl);
    prep_rm<<<PREP_GRID, 256>>>(qkv, 3 * C, 2 * C, 1.0f,   vh, vl);
    fmha_kernel<true><<<fgrid, 128, FMHA_SMEM>>>(qh, ql, kth, ktl, vh, vl, attn2);
    bgemm_kernel<1><<<dim3(C / BN, M / BM), 128, BG_SMEM>>>(
        attn2, wao2, attn_out_b, x, x1, nullptr, M, C, 3 * C);

    // cross-attention
    ln_kernel<<<M, 256>>>(x1, lnc_g, lnc_b, h2);
    bgemm_kernel<0><<<dim3(C / BN, M / BM), 128, BG_SMEM>>>(
        h2, wq2, q_b, nullptr, q2f, nullptr, M, C, 3 * C);
    bgemm_kernel<0><<<dim3(2 * C / BN, M / BM), 128, BG_SMEM>>>(
        ctx2, wkv2, kv_b, nullptr, kvf, nullptr, M, 2 * C, 3 * C);
    prep_rm<<<PREP_GRID, 256>>>(q2f, C,     0, 0.125f, qh, ql);
    prep_tr<<<PREP_GRID, 256>>>(kvf, 2 * C, 0,         kth, ktl);
    prep_rm<<<PREP_GRID, 256>>>(kvf, 2 * C, C, 1.0f,   vh, vl);
    fmha_kernel<false><<<fgrid, 128, FMHA_SMEM>>>(qh, ql, kth, ktl, vh, vl, attn2);
    bgemm_kernel<1><<<dim3(C / BN, M / BM), 128, BG_SMEM>>>(
        attn2, wco2, cross_out_b, x1, x2, nullptr, M, C, 3 * C);

    // FFN
    ln_kernel<<<M, 256>>>(x2, ln2_g, ln2_b, h2);
    bgemm_kernel<3><<<dim3(F / BN, M / BM), 128, BG_SMEM>>>(
        h2, wf1, ffn_b1, nullptr, nullptr, ffn2a, M, F, 3 * C);
    bgemm_kernel<1><<<dim3(C / BN, M / BM), 128, BG_SMEM>>>(
        ffn2a, wf2, ffn_b2, x2, out, nullptr, M, C, 3 * F);
}